// round 5
// baseline (speedup 1.0000x reference)
#include <cuda_runtime.h>
#include <math.h>

#define SEQ 2048
#define ND  128
#define NH  24
#define NC  32
#define BI  64
#define BJ  32
#define PI2 6.283185307179586f

typedef unsigned long long u64;

#define FMA2(d,a,b,c) asm("fma.rn.f32x2 %0,%1,%2,%3;":"=l"(d):"l"(a),"l"(b),"l"(c))
#define MUL2(d,a,b)   asm("mul.rn.f32x2 %0,%1,%2;":"=l"(d):"l"(a),"l"(b))
#define PACK2(d,lo,hi) asm("mov.b64 %0,{%1,%2};":"=l"(d):"f"(lo),"f"(hi))
#define UNPK2(lo,hi,v) asm("mov.b64 {%0,%1},%2;":"=f"(lo),"=f"(hi):"l"(v))

__device__ float g_k[NH*NC*SEQ];    // [h][c][i]
__device__ float g_q[NH*NC*SEQ];    // [h][c][j]
__device__ float g_v[NH*SEQ*ND];    // [h][j][d]
__device__ float g_part[NH*SEQ*ND];

__global__ __launch_bounds__(256) void proj_kq_kernel(
    const float* __restrict__ nodes, const float* __restrict__ pos,
    const float* __restrict__ rot,
    const float* __restrict__ w_nodes, const float* __restrict__ b_nodes,
    const float* __restrict__ w_pos, const float* __restrict__ b_pos,
    const float* __restrict__ w_rot)
{
    __shared__ float sn[16][128], sp[16][6], sr[16][4];
    const int i0 = blockIdx.x * 16, tid = threadIdx.x;
    for (int f = tid; f < 16*128; f += 256)
        sn[f>>7][f&127] = nodes[(i0+(f>>7))*128 + (f&127)];
    if (tid < 16) {
        int i = i0 + tid;
        float p0 = pos[i*3], p1 = pos[i*3+1], p2 = pos[i*3+2];
        sp[tid][0]=cosf(PI2*p0); sp[tid][1]=cosf(PI2*p1); sp[tid][2]=cosf(PI2*p2);
        sp[tid][3]=sinf(PI2*p0); sp[tid][4]=sinf(PI2*p1); sp[tid][5]=sinf(PI2*p2);
        sr[tid][0]=rot[i*4]; sr[tid][1]=rot[i*4+1]; sr[tid][2]=rot[i*4+2]; sr[tid][3]=rot[i*4+3];
    }
    __syncthreads();

    for (int o = tid; o < 512; o += 256) {   // nodes -> heads 0..7
        float acc[16], b = b_nodes[o];
        #pragma unroll
        for (int r = 0; r < 16; r++) acc[r] = b;
        const float4* w4 = (const float4*)(w_nodes + o*128);
        for (int k4 = 0; k4 < 32; k4++) {
            float4 wv = __ldg(w4 + k4);
            #pragma unroll
            for (int r = 0; r < 16; r++)
                acc[r] += wv.x*sn[r][4*k4] + wv.y*sn[r][4*k4+1] + wv.z*sn[r][4*k4+2] + wv.w*sn[r][4*k4+3];
        }
        int hh = o>>6, cx = o&63;
        float* dst = ((cx<32)?g_k:g_q) + (hh*NC + (cx&31))*SEQ + i0;
        #pragma unroll
        for (int r4 = 0; r4 < 4; r4++)
            ((float4*)dst)[r4] = make_float4(acc[4*r4],acc[4*r4+1],acc[4*r4+2],acc[4*r4+3]);
    }
    for (int o = tid; o < 512; o += 256) {   // pos -> heads 8..15
        float acc[16], b = b_pos[o];
        #pragma unroll
        for (int r = 0; r < 16; r++) acc[r] = b;
        const float* w = w_pos + o*6;
        for (int kk = 0; kk < 6; kk++) {
            float wv = __ldg(w+kk);
            #pragma unroll
            for (int r = 0; r < 16; r++) acc[r] += wv * sp[r][kk];
        }
        int hh = (o>>6)+8, cx = o&63;
        float* dst = ((cx<32)?g_k:g_q) + (hh*NC + (cx&31))*SEQ + i0;
        #pragma unroll
        for (int r4 = 0; r4 < 4; r4++)
            ((float4*)dst)[r4] = make_float4(acc[4*r4],acc[4*r4+1],acc[4*r4+2],acc[4*r4+3]);
    }
    for (int o = tid; o < 512; o += 256) {   // rot -> heads 16..23 (no bias)
        float acc[16];
        #pragma unroll
        for (int r = 0; r < 16; r++) acc[r] = 0.f;
        const float* w = w_rot + o*4;
        for (int kk = 0; kk < 4; kk++) {
            float wv = __ldg(w+kk);
            #pragma unroll
            for (int r = 0; r < 16; r++) acc[r] += wv * sr[r][kk];
        }
        int hh = (o>>6)+16, cx = o&63;
        float* dst = ((cx<32)?g_k:g_q) + (hh*NC + (cx&31))*SEQ + i0;
        #pragma unroll
        for (int r4 = 0; r4 < 4; r4++)
            ((float4*)dst)[r4] = make_float4(acc[4*r4],acc[4*r4+1],acc[4*r4+2],acc[4*r4+3]);
    }
}

// tiled GEMM: [S,3072] = nodes @ w^T + b, into g_v [h][j][d]
__global__ __launch_bounds__(256) void proj_val_kernel(
    const float* __restrict__ nodes,
    const float* __restrict__ w_values, const float* __restrict__ b_values)
{
    __shared__ float sa[32][128];
    __shared__ float sw[256][17];
    const int i0 = blockIdx.x*32, o0 = blockIdx.y*256, tid = threadIdx.x;
    const int g_i = tid>>5, g_o = tid&31;

    for (int f = tid; f < 32*128; f += 256)
        sa[f>>7][f&127] = nodes[(i0+(f>>7))*128 + (f&127)];

    float acc[4][8];
    #pragma unroll
    for (int e = 0; e < 8; e++) {
        float b = b_values[o0 + g_o + 32*e];
        #pragma unroll
        for (int r = 0; r < 4; r++) acc[r][e] = b;
    }
    for (int ks = 0; ks < 8; ks++) {
        __syncthreads();
        for (int f = tid; f < 256*16; f += 256)
            sw[f>>4][f&15] = w_values[(o0+(f>>4))*128 + ks*16 + (f&15)];
        __syncthreads();
        #pragma unroll 4
        for (int c = 0; c < 16; c++) {
            float a[4];
            #pragma unroll
            for (int r = 0; r < 4; r++) a[r] = sa[4*g_i+r][ks*16+c];
            #pragma unroll
            for (int e = 0; e < 8; e++) {
                float wv = sw[g_o+32*e][c];
                #pragma unroll
                for (int r = 0; r < 4; r++) acc[r][e] += a[r]*wv;
            }
        }
    }
    #pragma unroll
    for (int e = 0; e < 8; e++) {
        int o = o0 + g_o + 32*e, h = o>>7, dd = o&127;
        #pragma unroll
        for (int r = 0; r < 4; r++)
            g_v[((size_t)h*SEQ + i0+4*g_i+r)*ND + dd] = acc[r][e];
    }
}

// attention: BI=64 rows x 1 head per block; smem-duplicated operands, all-FFMA2 core
__global__ __launch_bounds__(256) void attn_kernel()
{
    const int tid = threadIdx.x, h = blockIdx.y, i0 = blockIdx.x*BI;
    const int t_hi = tid>>4, t_lo = tid&15, krow = 4*t_hi;

    __shared__ __align__(8) float skT[NC][BI];   // 8KB  [c][i] row-pairs as u64
    __shared__ u64 sqD[NC][BJ];                  // 8KB  [c][j] (q,q)
    __shared__ u64 slD[BI][BJ];                  // 16KB [i][j] (p,p)
    __shared__ __align__(16) float sv[BJ][ND];   // 16KB [j][d] d-pairs as u64

    const float* gk = g_k + h*NC*SEQ + i0;
    for (int f = tid; f < NC*BI; f += 256)
        skT[f>>6][f&63] = gk[(f>>6)*SEQ + (f&63)];

    float m[4], s[4];
    u64 acc[4][4];                               // [row r][d-pair m], d = 32m+2t_lo
    #pragma unroll
    for (int r = 0; r < 4; r++) {
        m[r] = -1e30f; s[r] = 0.f;
        #pragma unroll
        for (int mm = 0; mm < 4; mm++) acc[r][mm] = 0ull;
    }

    const float* gq = g_q + h*NC*SEQ;
    const float* gv = g_v + (size_t)h*SEQ*ND;
    const bool sqh = (h >= 16);

    for (int j0 = 0; j0 < SEQ; j0 += BJ) {
        __syncthreads();
        for (int f = tid; f < NC*BJ; f += 256) {
            float qv = gq[(f>>5)*SEQ + j0 + (f&31)];
            u64 qd; PACK2(qd, qv, qv);
            sqD[f>>5][f&31] = qd;
        }
        for (int f = tid; f < BJ*ND/4; f += 256)
            ((float4*)sv[f>>5])[f&31] = ((const float4*)gv)[(size_t)(j0+(f>>5))*(ND/4) + (f&31)];
        __syncthreads();

        // QK: rows paired in k (u64 direct), q duplicated in smem. j = t_lo + 16*jj
        u64 l2[2][2];                            // [jj][ri] rows (krow+2ri, +1)
        l2[0][0]=0ull; l2[0][1]=0ull; l2[1][0]=0ull; l2[1][1]=0ull;
        #pragma unroll 8
        for (int cc = 0; cc < NC; cc++) {
            u64 k0 = *(const u64*)&skT[cc][krow];
            u64 k1 = *(const u64*)&skT[cc][krow+2];
            u64 q0 = sqD[cc][t_lo];
            u64 q1 = sqD[cc][t_lo+16];
            FMA2(l2[0][0], k0, q0, l2[0][0]);
            FMA2(l2[0][1], k1, q0, l2[0][1]);
            FMA2(l2[1][0], k0, q1, l2[1][0]);
            FMA2(l2[1][1], k1, q1, l2[1][1]);
        }
        float lg[4][2];
        #pragma unroll
        for (int jj = 0; jj < 2; jj++) {
            UNPK2(lg[0][jj], lg[1][jj], l2[jj][0]);
            UNPK2(lg[2][jj], lg[3][jj], l2[jj][1]);
        }
        if (sqh)
            #pragma unroll
            for (int r = 0; r < 4; r++) { lg[r][0] *= lg[r][0]; lg[r][1] *= lg[r][1]; }

        // online softmax per row (16-lane half-warp reductions)
        float ca[4];
        #pragma unroll
        for (int r = 0; r < 4; r++) {
            float cm = fmaxf(lg[r][0], lg[r][1]);
            #pragma unroll
            for (int off = 8; off > 0; off >>= 1)
                cm = fmaxf(cm, __shfl_xor_sync(0xffffffffu, cm, off));
            float nm = fmaxf(m[r], cm);
            ca[r] = __expf(m[r] - nm); m[r] = nm;
            float p0 = __expf(lg[r][0] - nm), p1 = __expf(lg[r][1] - nm);
            float cs = p0 + p1;
            #pragma unroll
            for (int off = 8; off > 0; off >>= 1)
                cs += __shfl_xor_sync(0xffffffffu, cs, off);
            s[r] = s[r]*ca[r] + cs;
            u64 d0, d1; PACK2(d0, p0, p0); PACK2(d1, p1, p1);
            slD[krow+r][t_lo] = d0;
            slD[krow+r][t_lo+16] = d1;
        }
        #pragma unroll
        for (int r = 0; r < 4; r++) {
            u64 c2; PACK2(c2, ca[r], ca[r]);
            #pragma unroll
            for (int mm = 0; mm < 4; mm++) MUL2(acc[r][mm], acc[r][mm], c2);
        }
        __syncwarp();

        // PV: v d-pairs direct u64, probs duplicated in smem (broadcast loads)
        #pragma unroll 4
        for (int jj = 0; jj < BJ; jj++) {
            u64 v2[4];
            #pragma unroll
            for (int mm = 0; mm < 4; mm++)
                v2[mm] = *(const u64*)&sv[jj][32*mm + 2*t_lo];
            #pragma unroll
            for (int r = 0; r < 4; r++) {
                u64 p2 = slD[krow+r][jj];
                #pragma unroll
                for (int mm = 0; mm < 4; mm++)
                    FMA2(acc[r][mm], p2, v2[mm], acc[r][mm]);
            }
        }
        __syncwarp();
    }

    float* gp = g_part + (size_t)h*SEQ*ND;
    #pragma unroll
    for (int r = 0; r < 4; r++) {
        float inv = 1.f / s[r];
        #pragma unroll
        for (int mm = 0; mm < 4; mm++) {
            float x, y; UNPK2(x, y, acc[r][mm]);
            *(float2*)&gp[(size_t)(i0+krow+r)*ND + 32*mm + 2*t_lo] = make_float2(x*inv, y*inv);
        }
    }
}

__global__ __launch_bounds__(256) void reduce_kernel(float* __restrict__ out)
{
    int idx = blockIdx.x*256 + threadIdx.x;
    float s = 0.f;
    #pragma unroll
    for (int hh = 0; hh < NH; hh++) s += g_part[(size_t)hh*SEQ*ND + idx];
    out[idx] = s;
}

extern "C" void kernel_launch(void* const* d_in, const int* in_sizes, int n_in,
                              void* d_out, int out_size)
{
    const float* nodes = (const float*)d_in[0];
    const float* pos   = (const float*)d_in[1];
    const float* rot   = (const float*)d_in[2];

    proj_kq_kernel<<<SEQ/16, 256>>>(nodes, pos, rot,
        (const float*)d_in[3], (const float*)d_in[4],
        (const float*)d_in[5], (const float*)d_in[6], (const float*)d_in[7]);
    dim3 gv(SEQ/32, 3072/256);
    proj_val_kernel<<<gv, 256>>>(nodes, (const float*)d_in[8], (const float*)d_in[9]);
    dim3 ga(SEQ/BI, NH);
    attn_kernel<<<ga, 256>>>();
    reduce_kernel<<<(SEQ*ND)/256, 256>>>((float*)d_out);
}

// round 6
// speedup vs baseline: 2.3357x; 2.3357x over previous
#include <cuda_runtime.h>
#include <math.h>

#define SEQ 2048
#define ND  128
#define NH  24
#define NC  32
#define PI2 6.283185307179586f

typedef unsigned long long u64;
typedef unsigned int u32;

__device__ float g_k[NH*NC*SEQ];     // [h][c][i]
__device__ float g_q[NH*NC*SEQ];     // [h][c][j]
__device__ float g_v[NH*SEQ*ND];     // [h][j][d]
__device__ u64   g_qp[NH*64*1024];   // packed tf32 q frag-pairs (hi/lo)
__device__ u64   g_vp[NH*64*2048];   // packed tf32 v frag-pairs
__device__ float g_part[NH*SEQ*ND];

__device__ __forceinline__ u32 tf32b(float f){ u32 r; asm("cvt.rna.tf32.f32 %0,%1;":"=r"(r):"f"(f)); return r; }

__device__ __forceinline__ void mma8(float* c, const u32* a, u32 b0, u32 b1){
    asm volatile("mma.sync.aligned.m16n8k8.row.col.f32.tf32.tf32.f32 "
        "{%0,%1,%2,%3},{%4,%5,%6,%7},{%8,%9},{%0,%1,%2,%3};"
        : "+f"(c[0]),"+f"(c[1]),"+f"(c[2]),"+f"(c[3])
        : "r"(a[0]),"r"(a[1]),"r"(a[2]),"r"(a[3]),"r"(b0),"r"(b1));
}

__global__ __launch_bounds__(256) void proj_kq_kernel(
    const float* __restrict__ nodes, const float* __restrict__ pos,
    const float* __restrict__ rot,
    const float* __restrict__ w_nodes, const float* __restrict__ b_nodes,
    const float* __restrict__ w_pos, const float* __restrict__ b_pos,
    const float* __restrict__ w_rot)
{
    __shared__ float sn[16][128], sp[16][6], sr[16][4];
    const int i0 = blockIdx.x * 16, tid = threadIdx.x;
    for (int f = tid; f < 16*128; f += 256)
        sn[f>>7][f&127] = nodes[(i0+(f>>7))*128 + (f&127)];
    if (tid < 16) {
        int i = i0 + tid;
        float p0 = pos[i*3], p1 = pos[i*3+1], p2 = pos[i*3+2];
        sp[tid][0]=cosf(PI2*p0); sp[tid][1]=cosf(PI2*p1); sp[tid][2]=cosf(PI2*p2);
        sp[tid][3]=sinf(PI2*p0); sp[tid][4]=sinf(PI2*p1); sp[tid][5]=sinf(PI2*p2);
        sr[tid][0]=rot[i*4]; sr[tid][1]=rot[i*4+1]; sr[tid][2]=rot[i*4+2]; sr[tid][3]=rot[i*4+3];
    }
    __syncthreads();

    for (int o = tid; o < 512; o += 256) {
        float acc[16], b = b_nodes[o];
        #pragma unroll
        for (int r = 0; r < 16; r++) acc[r] = b;
        const float4* w4 = (const float4*)(w_nodes + o*128);
        for (int k4 = 0; k4 < 32; k4++) {
            float4 wv = __ldg(w4 + k4);
            #pragma unroll
            for (int r = 0; r < 16; r++)
                acc[r] += wv.x*sn[r][4*k4] + wv.y*sn[r][4*k4+1] + wv.z*sn[r][4*k4+2] + wv.w*sn[r][4*k4+3];
        }
        int hh = o>>6, cx = o&63;
        float* dst = ((cx<32)?g_k:g_q) + (hh*NC + (cx&31))*SEQ + i0;
        #pragma unroll
        for (int r4 = 0; r4 < 4; r4++)
            ((float4*)dst)[r4] = make_float4(acc[4*r4],acc[4*r4+1],acc[4*r4+2],acc[4*r4+3]);
    }
    for (int o = tid; o < 512; o += 256) {
        float acc[16], b = b_pos[o];
        #pragma unroll
        for (int r = 0; r < 16; r++) acc[r] = b;
        const float* w = w_pos + o*6;
        for (int kk = 0; kk < 6; kk++) {
            float wv = __ldg(w+kk);
            #pragma unroll
            for (int r = 0; r < 16; r++) acc[r] += wv * sp[r][kk];
        }
        int hh = (o>>6)+8, cx = o&63;
        float* dst = ((cx<32)?g_k:g_q) + (hh*NC + (cx&31))*SEQ + i0;
        #pragma unroll
        for (int r4 = 0; r4 < 4; r4++)
            ((float4*)dst)[r4] = make_float4(acc[4*r4],acc[4*r4+1],acc[4*r4+2],acc[4*r4+3]);
    }
    for (int o = tid; o < 512; o += 256) {
        float acc[16];
        #pragma unroll
        for (int r = 0; r < 16; r++) acc[r] = 0.f;
        const float* w = w_rot + o*4;
        for (int kk = 0; kk < 4; kk++) {
            float wv = __ldg(w+kk);
            #pragma unroll
            for (int r = 0; r < 16; r++) acc[r] += wv * sr[r][kk];
        }
        int hh = (o>>6)+16, cx = o&63;
        float* dst = ((cx<32)?g_k:g_q) + (hh*NC + (cx&31))*SEQ + i0;
        #pragma unroll
        for (int r4 = 0; r4 < 4; r4++)
            ((float4*)dst)[r4] = make_float4(acc[4*r4],acc[4*r4+1],acc[4*r4+2],acc[4*r4+3]);
    }
}

__global__ __launch_bounds__(256) void proj_val_kernel(
    const float* __restrict__ nodes,
    const float* __restrict__ w_values, const float* __restrict__ b_values)
{
    __shared__ float sa[32][128];
    __shared__ float sw[256][17];
    const int i0 = blockIdx.x*32, o0 = blockIdx.y*256, tid = threadIdx.x;
    const int g_i = tid>>5, g_o = tid&31;

    for (int f = tid; f < 32*128; f += 256)
        sa[f>>7][f&127] = nodes[(i0+(f>>7))*128 + (f&127)];

    float acc[4][8];
    #pragma unroll
    for (int e = 0; e < 8; e++) {
        float b = b_values[o0 + g_o + 32*e];
        #pragma unroll
        for (int r = 0; r < 4; r++) acc[r][e] = b;
    }
    for (int ks = 0; ks < 8; ks++) {
        __syncthreads();
        for (int f = tid; f < 256*16; f += 256)
            sw[f>>4][f&15] = w_values[(o0+(f>>4))*128 + ks*16 + (f&15)];
        __syncthreads();
        #pragma unroll 4
        for (int c = 0; c < 16; c++) {
            float a[4];
            #pragma unroll
            for (int r = 0; r < 4; r++) a[r] = sa[4*g_i+r][ks*16+c];
            #pragma unroll
            for (int e = 0; e < 8; e++) {
                float wv = sw[g_o+32*e][c];
                #pragma unroll
                for (int r = 0; r < 4; r++) acc[r][e] += a[r]*wv;
            }
        }
    }
    #pragma unroll
    for (int e = 0; e < 8; e++) {
        int o = o0 + g_o + 32*e, h = o>>7, dd = o&127;
        #pragma unroll
        for (int r = 0; r < 4; r++)
            g_v[((size_t)h*SEQ + i0+4*g_i+r)*ND + dd] = acc[r][e];
    }
}

// pack q into mma B-frag u64 pairs (hi/lo split for 3-pass tf32)
__global__ __launch_bounds__(256) void pack_q_kernel()
{
    int id = blockIdx.x*256 + threadIdx.x;           // 786432 total
    int l = id&31, nt = (id>>5)&3, kt = (id>>7)&3, ch = (id>>9)&63, h = id>>15;
    int c = kt*8 + (l&3), j = ch*32 + nt*8 + (l>>2);
    float q1 = g_q[(h*NC+c)*SEQ + j];
    float q2 = g_q[(h*NC+c+4)*SEQ + j];
    u32 h1 = tf32b(q1), h2 = tf32b(q2);
    u32 l1 = tf32b(q1 - __uint_as_float(h1));
    u32 l2 = tf32b(q2 - __uint_as_float(h2));
    size_t base = (size_t)(id>>9)*1024 + (id&511);
    g_qp[base]       = ((u64)h2<<32) | h1;
    g_qp[base + 512] = ((u64)l2<<32) | l1;
}

// pack v into mma B-frag u64 pairs (tf32)
__global__ __launch_bounds__(256) void pack_v_kernel()
{
    int id = blockIdx.x*256 + threadIdx.x;           // 3145728 total
    int l = id&31, nt = (id>>5)&15, kt = (id>>9)&3, ch = (id>>11)&63, h = id>>17;
    int j = ch*32 + kt*8 + (l&3), d = nt*8 + (l>>2);
    float v1 = g_v[((size_t)h*SEQ + j)*ND + d];
    float v2 = g_v[((size_t)h*SEQ + j+4)*ND + d];
    g_vp[id] = ((u64)tf32b(v2)<<32) | tf32b(v1);
}

// attention: BI=64 rows, 4 warps, mma.sync tf32 (QK 3-pass split, PV 1-pass)
__global__ __launch_bounds__(128) void attn_kernel()
{
    const int tid = threadIdx.x, w = tid>>5, lane = tid&31;
    const int g = lane>>2, tig = lane&3;
    const int h = blockIdx.y, i0 = blockIdx.x*64, iw = i0 + 16*w;

    __shared__ u64 sqp[1024];          // 8KB  q pairs (hi 512, lo 512)
    __shared__ u64 svp[2048];          // 16KB v pairs
    __shared__ u32 pP[4][16][36];      // 9KB  P (tf32 bits), per-warp

    // k A-fragments, hi/lo split (fp32-accurate logits)
    u32 ah[4][4], al[4][4];
    #pragma unroll
    for (int kt = 0; kt < 4; kt++) {
        float kv[4];
        kv[0] = g_k[(h*NC + kt*8+tig  )*SEQ + iw + g];
        kv[1] = g_k[(h*NC + kt*8+tig  )*SEQ + iw + g + 8];
        kv[2] = g_k[(h*NC + kt*8+tig+4)*SEQ + iw + g];
        kv[3] = g_k[(h*NC + kt*8+tig+4)*SEQ + iw + g + 8];
        #pragma unroll
        for (int e = 0; e < 4; e++) {
            ah[kt][e] = tf32b(kv[e]);
            al[kt][e] = tf32b(kv[e] - __uint_as_float(ah[kt][e]));
        }
    }

    float o[16][4];
    #pragma unroll
    for (int nt = 0; nt < 16; nt++) { o[nt][0]=0.f; o[nt][1]=0.f; o[nt][2]=0.f; o[nt][3]=0.f; }
    float m0 = -1e30f, m1 = -1e30f, s0 = 0.f, s1 = 0.f;

    const u64* gqp = g_qp + (size_t)h*64*1024;
    const u64* gvp = g_vp + (size_t)h*64*2048;
    const bool sqh = (h >= 16);

    for (int ch = 0; ch < 64; ch++) {
        __syncthreads();
        const float4* srcq = (const float4*)(gqp + (size_t)ch*1024);
        for (int f = tid; f < 512; f += 128) ((float4*)sqp)[f] = srcq[f];
        const float4* srcv = (const float4*)(gvp + (size_t)ch*2048);
        for (int f = tid; f < 1024; f += 128) ((float4*)svp)[f] = srcv[f];
        __syncthreads();

        // QK: 3-pass split tf32
        float C[4][4];
        #pragma unroll
        for (int nt = 0; nt < 4; nt++) { C[nt][0]=0.f; C[nt][1]=0.f; C[nt][2]=0.f; C[nt][3]=0.f; }
        #pragma unroll
        for (int kt = 0; kt < 4; kt++) {
            #pragma unroll
            for (int nt = 0; nt < 4; nt++) {
                u64 bh = sqp[kt*128 + nt*32 + lane];
                u64 bl = sqp[512 + kt*128 + nt*32 + lane];
                u32 bh0 = (u32)bh, bh1 = (u32)(bh>>32);
                u32 bl0 = (u32)bl, bl1 = (u32)(bl>>32);
                mma8(C[nt], ah[kt], bh0, bh1);
                mma8(C[nt], al[kt], bh0, bh1);
                mma8(C[nt], ah[kt], bl0, bl1);
            }
        }
        if (sqh) {
            #pragma unroll
            for (int nt = 0; nt < 4; nt++) {
                C[nt][0]*=C[nt][0]; C[nt][1]*=C[nt][1]; C[nt][2]*=C[nt][2]; C[nt][3]*=C[nt][3];
            }
        }

        // online softmax: thread owns rows g (C[][0..1]) and g+8 (C[][2..3])
        float cm0 = -1e30f, cm1 = -1e30f;
        #pragma unroll
        for (int nt = 0; nt < 4; nt++) {
            cm0 = fmaxf(cm0, fmaxf(C[nt][0], C[nt][1]));
            cm1 = fmaxf(cm1, fmaxf(C[nt][2], C[nt][3]));
        }
        cm0 = fmaxf(cm0, __shfl_xor_sync(0xffffffffu, cm0, 1));
        cm0 = fmaxf(cm0, __shfl_xor_sync(0xffffffffu, cm0, 2));
        cm1 = fmaxf(cm1, __shfl_xor_sync(0xffffffffu, cm1, 1));
        cm1 = fmaxf(cm1, __shfl_xor_sync(0xffffffffu, cm1, 2));
        float nm0 = fmaxf(m0, cm0), nm1 = fmaxf(m1, cm1);
        float ca0 = __expf(m0 - nm0), ca1 = __expf(m1 - nm1);
        m0 = nm0; m1 = nm1;

        float p[4][4];
        float cs0 = 0.f, cs1 = 0.f;
        #pragma unroll
        for (int nt = 0; nt < 4; nt++) {
            p[nt][0] = __expf(C[nt][0] - nm0);
            p[nt][1] = __expf(C[nt][1] - nm0);
            p[nt][2] = __expf(C[nt][2] - nm1);
            p[nt][3] = __expf(C[nt][3] - nm1);
            cs0 += p[nt][0] + p[nt][1];
            cs1 += p[nt][2] + p[nt][3];
        }
        cs0 += __shfl_xor_sync(0xffffffffu, cs0, 1);
        cs0 += __shfl_xor_sync(0xffffffffu, cs0, 2);
        cs1 += __shfl_xor_sync(0xffffffffu, cs1, 1);
        cs1 += __shfl_xor_sync(0xffffffffu, cs1, 2);
        s0 = s0*ca0 + cs0;
        s1 = s1*ca1 + cs1;
        #pragma unroll
        for (int nt = 0; nt < 16; nt++) {
            o[nt][0] *= ca0; o[nt][1] *= ca0;
            o[nt][2] *= ca1; o[nt][3] *= ca1;
        }

        // P -> smem (tf32 bits), then A-fragments
        #pragma unroll
        for (int nt = 0; nt < 4; nt++) {
            u64 pr0 = ((u64)tf32b(p[nt][1])<<32) | tf32b(p[nt][0]);
            u64 pr1 = ((u64)tf32b(p[nt][3])<<32) | tf32b(p[nt][2]);
            *(u64*)&pP[w][g][8*nt + 2*tig]     = pr0;
            *(u64*)&pP[w][g+8][8*nt + 2*tig]   = pr1;
        }
        __syncwarp();
        u32 pa[4][4];
        #pragma unroll
        for (int kt = 0; kt < 4; kt++) {
            pa[kt][0] = pP[w][g  ][kt*8 + tig];
            pa[kt][1] = pP[w][g+8][kt*8 + tig];
            pa[kt][2] = pP[w][g  ][kt*8 + tig + 4];
            pa[kt][3] = pP[w][g+8][kt*8 + tig + 4];
        }

        // PV
        #pragma unroll
        for (int kt = 0; kt < 4; kt++) {
            #pragma unroll
            for (int nt = 0; nt < 16; nt++) {
                u64 bv = svp[kt*512 + nt*32 + lane];
                mma8(o[nt], pa[kt], (u32)bv, (u32)(bv>>32));
            }
        }
    }

    float inv0 = 1.f/s0, inv1 = 1.f/s1;
    float* gp = g_part + ((size_t)h*SEQ + iw)*ND;
    #pragma unroll
    for (int nt = 0; nt < 16; nt++) {
        *(float2*)&gp[(size_t)g*ND + nt*8 + 2*tig]     = make_float2(o[nt][0]*inv0, o[nt][1]*inv0);
        *(float2*)&gp[(size_t)(g+8)*ND + nt*8 + 2*tig] = make_float2(o[nt][2]*inv1, o[nt][3]*inv1);
    }
}

__global__ __launch_bounds__(256) void reduce_kernel(float* __restrict__ out)
{
    int idx = blockIdx.x*256 + threadIdx.x;
    float s = 0.f;
    #pragma unroll
    for (int hh = 0; hh < NH; hh++) s += g_part[(size_t)hh*SEQ*ND + idx];
    out[idx] = s;
}

extern "C" void kernel_launch(void* const* d_in, const int* in_sizes, int n_in,
                              void* d_out, int out_size)
{
    const float* nodes = (const float*)d_in[0];
    const float* pos   = (const float*)d_in[1];
    const float* rot   = (const float*)d_in[2];

    proj_kq_kernel<<<SEQ/16, 256>>>(nodes, pos, rot,
        (const float*)d_in[3], (const float*)d_in[4],
        (const float*)d_in[5], (const float*)d_in[6], (const float*)d_in[7]);
    dim3 gv(SEQ/32, 3072/256);
    proj_val_kernel<<<gv, 256>>>(nodes, (const float*)d_in[8], (const float*)d_in[9]);
    pack_q_kernel<<<3072, 256>>>();
    pack_v_kernel<<<12288, 256>>>();
    dim3 ga(SEQ/64, NH);
    attn_kernel<<<ga, 128>>>();
    reduce_kernel<<<(SEQ*ND)/256, 256>>>((float*)d_out);
}

// round 7
// speedup vs baseline: 2.7858x; 1.1927x over previous
#include <cuda_runtime.h>
#include <math.h>

#define SEQ 2048
#define ND  128
#define NH  24
#define NC  32
#define PI2 6.283185307179586f

typedef unsigned long long u64;
typedef unsigned int u32;

__device__ float g_k[NH*NC*SEQ];     // [h][c][i]
__device__ float g_q[NH*NC*SEQ];     // [h][c][j]
__device__ float g_v[NH*SEQ*ND];     // [h][j][d]
__device__ u64   g_qp[NH*64*1024];   // packed tf32 q frag-pairs (hi/lo)
__device__ u64   g_vp[NH*64*2048];   // packed tf32 v frag-pairs
__device__ float g_part[NH*SEQ*ND];

__device__ __forceinline__ u32 tf32b(float f){ u32 r; asm("cvt.rna.tf32.f32 %0,%1;":"=r"(r):"f"(f)); return r; }

__device__ __forceinline__ void mma8(float* c, const u32* a, u32 b0, u32 b1){
    asm volatile("mma.sync.aligned.m16n8k8.row.col.f32.tf32.tf32.f32 "
        "{%0,%1,%2,%3},{%4,%5,%6,%7},{%8,%9},{%0,%1,%2,%3};"
        : "+f"(c[0]),"+f"(c[1]),"+f"(c[2]),"+f"(c[3])
        : "r"(a[0]),"r"(a[1]),"r"(a[2]),"r"(a[3]),"r"(b0),"r"(b1));
}

__device__ __forceinline__ void cpa16(void* smem, const void* gmem){
    u32 s = (u32)__cvta_generic_to_shared(smem);
    asm volatile("cp.async.cg.shared.global [%0], [%1], 16;" :: "r"(s), "l"(gmem));
}
#define CP_COMMIT() asm volatile("cp.async.commit_group;")
#define CP_WAIT1()  asm volatile("cp.async.wait_group 1;")

__global__ __launch_bounds__(256) void proj_kq_kernel(
    const float* __restrict__ nodes, const float* __restrict__ pos,
    const float* __restrict__ rot,
    const float* __restrict__ w_nodes, const float* __restrict__ b_nodes,
    const float* __restrict__ w_pos, const float* __restrict__ b_pos,
    const float* __restrict__ w_rot)
{
    __shared__ float sn[16][128], sp[16][6], sr[16][4];
    const int i0 = blockIdx.x * 16, tid = threadIdx.x;
    for (int f = tid; f < 16*128; f += 256)
        sn[f>>7][f&127] = nodes[(i0+(f>>7))*128 + (f&127)];
    if (tid < 16) {
        int i = i0 + tid;
        float p0 = pos[i*3], p1 = pos[i*3+1], p2 = pos[i*3+2];
        sp[tid][0]=cosf(PI2*p0); sp[tid][1]=cosf(PI2*p1); sp[tid][2]=cosf(PI2*p2);
        sp[tid][3]=sinf(PI2*p0); sp[tid][4]=sinf(PI2*p1); sp[tid][5]=sinf(PI2*p2);
        sr[tid][0]=rot[i*4]; sr[tid][1]=rot[i*4+1]; sr[tid][2]=rot[i*4+2]; sr[tid][3]=rot[i*4+3];
    }
    __syncthreads();

    for (int o = tid; o < 512; o += 256) {
        float acc[16], b = b_nodes[o];
        #pragma unroll
        for (int r = 0; r < 16; r++) acc[r] = b;
        const float4* w4 = (const float4*)(w_nodes + o*128);
        for (int k4 = 0; k4 < 32; k4++) {
            float4 wv = __ldg(w4 + k4);
            #pragma unroll
            for (int r = 0; r < 16; r++)
                acc[r] += wv.x*sn[r][4*k4] + wv.y*sn[r][4*k4+1] + wv.z*sn[r][4*k4+2] + wv.w*sn[r][4*k4+3];
        }
        int hh = o>>6, cx = o&63;
        float* dst = ((cx<32)?g_k:g_q) + (hh*NC + (cx&31))*SEQ + i0;
        #pragma unroll
        for (int r4 = 0; r4 < 4; r4++)
            ((float4*)dst)[r4] = make_float4(acc[4*r4],acc[4*r4+1],acc[4*r4+2],acc[4*r4+3]);
    }
    for (int o = tid; o < 512; o += 256) {
        float acc[16], b = b_pos[o];
        #pragma unroll
        for (int r = 0; r < 16; r++) acc[r] = b;
        const float* w = w_pos + o*6;
        for (int kk = 0; kk < 6; kk++) {
            float wv = __ldg(w+kk);
            #pragma unroll
            for (int r = 0; r < 16; r++) acc[r] += wv * sp[r][kk];
        }
        int hh = (o>>6)+8, cx = o&63;
        float* dst = ((cx<32)?g_k:g_q) + (hh*NC + (cx&31))*SEQ + i0;
        #pragma unroll
        for (int r4 = 0; r4 < 4; r4++)
            ((float4*)dst)[r4] = make_float4(acc[4*r4],acc[4*r4+1],acc[4*r4+2],acc[4*r4+3]);
    }
    for (int o = tid; o < 512; o += 256) {
        float acc[16];
        #pragma unroll
        for (int r = 0; r < 16; r++) acc[r] = 0.f;
        const float* w = w_rot + o*4;
        for (int kk = 0; kk < 4; kk++) {
            float wv = __ldg(w+kk);
            #pragma unroll
            for (int r = 0; r < 16; r++) acc[r] += wv * sr[r][kk];
        }
        int hh = (o>>6)+16, cx = o&63;
        float* dst = ((cx<32)?g_k:g_q) + (hh*NC + (cx&31))*SEQ + i0;
        #pragma unroll
        for (int r4 = 0; r4 < 4; r4++)
            ((float4*)dst)[r4] = make_float4(acc[4*r4],acc[4*r4+1],acc[4*r4+2],acc[4*r4+3]);
    }
}

__global__ __launch_bounds__(256) void proj_val_kernel(
    const float* __restrict__ nodes,
    const float* __restrict__ w_values, const float* __restrict__ b_values)
{
    __shared__ float sa[32][128];
    __shared__ float sw[256][17];
    const int i0 = blockIdx.x*32, o0 = blockIdx.y*256, tid = threadIdx.x;
    const int g_i = tid>>5, g_o = tid&31;

    for (int f = tid; f < 32*128; f += 256)
        sa[f>>7][f&127] = nodes[(i0+(f>>7))*128 + (f&127)];

    float acc[4][8];
    #pragma unroll
    for (int e = 0; e < 8; e++) {
        float b = b_values[o0 + g_o + 32*e];
        #pragma unroll
        for (int r = 0; r < 4; r++) acc[r][e] = b;
    }
    for (int ks = 0; ks < 8; ks++) {
        __syncthreads();
        for (int f = tid; f < 256*16; f += 256)
            sw[f>>4][f&15] = w_values[(o0+(f>>4))*128 + ks*16 + (f&15)];
        __syncthreads();
        #pragma unroll 4
        for (int c = 0; c < 16; c++) {
            float a[4];
            #pragma unroll
            for (int r = 0; r < 4; r++) a[r] = sa[4*g_i+r][ks*16+c];
            #pragma unroll
            for (int e = 0; e < 8; e++) {
                float wv = sw[g_o+32*e][c];
                #pragma unroll
                for (int r = 0; r < 4; r++) acc[r][e] += a[r]*wv;
            }
        }
    }
    #pragma unroll
    for (int e = 0; e < 8; e++) {
        int o = o0 + g_o + 32*e, h = o>>7, dd = o&127;
        #pragma unroll
        for (int r = 0; r < 4; r++)
            g_v[((size_t)h*SEQ + i0+4*g_i+r)*ND + dd] = acc[r][e];
    }
}

__global__ __launch_bounds__(256) void pack_q_kernel()
{
    int id = blockIdx.x*256 + threadIdx.x;
    int l = id&31, nt = (id>>5)&3, kt = (id>>7)&3, ch = (id>>9)&63, h = id>>15;
    int c = kt*8 + (l&3), j = ch*32 + nt*8 + (l>>2);
    float q1 = g_q[(h*NC+c)*SEQ + j];
    float q2 = g_q[(h*NC+c+4)*SEQ + j];
    u32 h1 = tf32b(q1), h2 = tf32b(q2);
    u32 l1 = tf32b(q1 - __uint_as_float(h1));
    u32 l2 = tf32b(q2 - __uint_as_float(h2));
    size_t base = (size_t)(id>>9)*1024 + (id&511);
    g_qp[base]       = ((u64)h2<<32) | h1;
    g_qp[base + 512] = ((u64)l2<<32) | l1;
}

__global__ __launch_bounds__(256) void pack_v_kernel()
{
    int id = blockIdx.x*256 + threadIdx.x;
    int l = id&31, nt = (id>>5)&15, kt = (id>>9)&3, ch = (id>>11)&63, h = id>>17;
    int j = ch*32 + kt*8 + (l&3), d = nt*8 + (l>>2);
    float v1 = g_v[((size_t)h*SEQ + j)*ND + d];
    float v2 = g_v[((size_t)h*SEQ + j+4)*ND + d];
    g_vp[id] = ((u64)tf32b(v2)<<32) | tf32b(v1);
}

// attention: 128 rows/block, 8 warps, double-buffered cp.async staging
#define SMEM_DYN (2*8192 + 2*16384 + 8*2304)
__global__ __launch_bounds__(256) void attn_kernel()
{
    extern __shared__ __align__(16) unsigned char dsm[];
    u64* qbuf = (u64*)dsm;                 // 2 x 1024 u64
    u64* vbuf = (u64*)(dsm + 16384);       // 2 x 2048 u64

    const int tid = threadIdx.x, w = tid>>5, lane = tid&31;
    const int g = lane>>2, tig = lane&3;
    const int h = blockIdx.y, i0 = blockIdx.x*128, iw = i0 + 16*w;
    u32* pP = (u32*)(dsm + 49152) + w*576; // [16][36] per warp

    // k A-fragments, hi/lo split
    u32 ah[4][4], al[4][4];
    #pragma unroll
    for (int kt = 0; kt < 4; kt++) {
        float kv[4];
        kv[0] = g_k[(h*NC + kt*8+tig  )*SEQ + iw + g];
        kv[1] = g_k[(h*NC + kt*8+tig  )*SEQ + iw + g + 8];
        kv[2] = g_k[(h*NC + kt*8+tig+4)*SEQ + iw + g];
        kv[3] = g_k[(h*NC + kt*8+tig+4)*SEQ + iw + g + 8];
        #pragma unroll
        for (int e = 0; e < 4; e++) {
            ah[kt][e] = tf32b(kv[e]);
            al[kt][e] = tf32b(kv[e] - __uint_as_float(ah[kt][e]));
        }
    }

    float o[16][4];
    #pragma unroll
    for (int nt = 0; nt < 16; nt++) { o[nt][0]=0.f; o[nt][1]=0.f; o[nt][2]=0.f; o[nt][3]=0.f; }
    float m0 = -1e30f, m1 = -1e30f, s0 = 0.f, s1 = 0.f;

    const u64* gqp = g_qp + (size_t)h*64*1024;
    const u64* gvp = g_vp + (size_t)h*64*2048;
    const bool sqh = (h >= 16);

    // prologue: stage chunk 0 into buffer 0
    {
        const float4* sq = (const float4*)gqp;
        const float4* sv = (const float4*)gvp;
        #pragma unroll
        for (int r = 0; r < 2; r++) cpa16((float4*)qbuf + tid + 256*r, sq + tid + 256*r);
        #pragma unroll
        for (int r = 0; r < 4; r++) cpa16((float4*)vbuf + tid + 256*r, sv + tid + 256*r);
        CP_COMMIT();
    }

    for (int ch = 0; ch < 64; ch++) {
        int cur = ch & 1;
        if (ch < 63) {
            int nb = (ch+1) & 1;
            const float4* sq = (const float4*)(gqp + (size_t)(ch+1)*1024);
            const float4* sv = (const float4*)(gvp + (size_t)(ch+1)*2048);
            #pragma unroll
            for (int r = 0; r < 2; r++) cpa16((float4*)(qbuf + nb*1024) + tid + 256*r, sq + tid + 256*r);
            #pragma unroll
            for (int r = 0; r < 4; r++) cpa16((float4*)(vbuf + nb*2048) + tid + 256*r, sv + tid + 256*r);
        }
        CP_COMMIT();
        CP_WAIT1();
        __syncthreads();

        const u64* sqp = qbuf + cur*1024;
        const u64* svp = vbuf + cur*2048;

        // QK: 3-pass split tf32
        float C[4][4];
        #pragma unroll
        for (int nt = 0; nt < 4; nt++) { C[nt][0]=0.f; C[nt][1]=0.f; C[nt][2]=0.f; C[nt][3]=0.f; }
        #pragma unroll
        for (int kt = 0; kt < 4; kt++) {
            #pragma unroll
            for (int nt = 0; nt < 4; nt++) {
                u64 bh = sqp[kt*128 + nt*32 + lane];
                u64 bl = sqp[512 + kt*128 + nt*32 + lane];
                u32 bh0 = (u32)bh, bh1 = (u32)(bh>>32);
                mma8(C[nt], ah[kt], bh0, bh1);
                mma8(C[nt], al[kt], bh0, bh1);
                mma8(C[nt], ah[kt], (u32)bl, (u32)(bl>>32));
            }
        }
        if (sqh) {
            #pragma unroll
            for (int nt = 0; nt < 4; nt++) {
                C[nt][0]*=C[nt][0]; C[nt][1]*=C[nt][1]; C[nt][2]*=C[nt][2]; C[nt][3]*=C[nt][3];
            }
        }

        float cm0 = -1e30f, cm1 = -1e30f;
        #pragma unroll
        for (int nt = 0; nt < 4; nt++) {
            cm0 = fmaxf(cm0, fmaxf(C[nt][0], C[nt][1]));
            cm1 = fmaxf(cm1, fmaxf(C[nt][2], C[nt][3]));
        }
        cm0 = fmaxf(cm0, __shfl_xor_sync(0xffffffffu, cm0, 1));
        cm0 = fmaxf(cm0, __shfl_xor_sync(0xffffffffu, cm0, 2));
        cm1 = fmaxf(cm1, __shfl_xor_sync(0xffffffffu, cm1, 1));
        cm1 = fmaxf(cm1, __shfl_xor_sync(0xffffffffu, cm1, 2));
        float nm0 = fmaxf(m0, cm0), nm1 = fmaxf(m1, cm1);
        bool noup = (nm0 == m0) & (nm1 == m1);
        float ca0 = __expf(m0 - nm0), ca1 = __expf(m1 - nm1);
        m0 = nm0; m1 = nm1;

        float p[4][4];
        float cs0 = 0.f, cs1 = 0.f;
        #pragma unroll
        for (int nt = 0; nt < 4; nt++) {
            p[nt][0] = __expf(C[nt][0] - nm0);
            p[nt][1] = __expf(C[nt][1] - nm0);
            p[nt][2] = __expf(C[nt][2] - nm1);
            p[nt][3] = __expf(C[nt][3] - nm1);
            cs0 += p[nt][0] + p[nt][1];
            cs1 += p[nt][2] + p[nt][3];
        }
        cs0 += __shfl_xor_sync(0xffffffffu, cs0, 1);
        cs0 += __shfl_xor_sync(0xffffffffu, cs0, 2);
        cs1 += __shfl_xor_sync(0xffffffffu, cs1, 1);
        cs1 += __shfl_xor_sync(0xffffffffu, cs1, 2);
        s0 = s0*ca0 + cs0;
        s1 = s1*ca1 + cs1;
        if (!__all_sync(0xffffffffu, noup)) {
            #pragma unroll
            for (int nt = 0; nt < 16; nt++) {
                o[nt][0] *= ca0; o[nt][1] *= ca0;
                o[nt][2] *= ca1; o[nt][3] *= ca1;
            }
        }

        // P -> per-warp smem tile, then A-fragments
        #pragma unroll
        for (int nt = 0; nt < 4; nt++) {
            u64 pr0 = ((u64)tf32b(p[nt][1])<<32) | tf32b(p[nt][0]);
            u64 pr1 = ((u64)tf32b(p[nt][3])<<32) | tf32b(p[nt][2]);
            *(u64*)&pP[g*36 + 8*nt + 2*tig]     = pr0;
            *(u64*)&pP[(g+8)*36 + 8*nt + 2*tig] = pr1;
        }
        __syncwarp();
        u32 pa[4][4];
        #pragma unroll
        for (int kt = 0; kt < 4; kt++) {
            pa[kt][0] = pP[g*36     + kt*8 + tig];
            pa[kt][1] = pP[(g+8)*36 + kt*8 + tig];
            pa[kt][2] = pP[g*36     + kt*8 + tig + 4];
            pa[kt][3] = pP[(g+8)*36 + kt*8 + tig + 4];
        }

        // PV
        #pragma unroll
        for (int kt = 0; kt < 4; kt++) {
            #pragma unroll
            for (int nt = 0; nt < 16; nt++) {
                u64 bv = svp[kt*512 + nt*32 + lane];
                mma8(o[nt], pa[kt], (u32)bv, (u32)(bv>>32));
            }
        }
        __syncthreads();
    }

    float inv0 = 1.f/s0, inv1 = 1.f/s1;
    float* gp = g_part + ((size_t)h*SEQ + iw)*ND;
    #pragma unroll
    for (int nt = 0; nt < 16; nt++) {
        *(float2*)&gp[(size_t)g*ND + nt*8 + 2*tig]     = make_float2(o[nt][0]*inv0, o[nt][1]*inv0);
        *(float2*)&gp[(size_t)(g+8)*ND + nt*8 + 2*tig] = make_float2(o[nt][2]*inv1, o[nt][3]*inv1);
    }
}

__global__ __launch_bounds__(256) void reduce_kernel(float* __restrict__ out)
{
    int idx = blockIdx.x*256 + threadIdx.x;
    float s = 0.f;
    #pragma unroll
    for (int hh = 0; hh < NH; hh++) s += g_part[(size_t)hh*SEQ*ND + idx];
    out[idx] = s;
}

extern "C" void kernel_launch(void* const* d_in, const int* in_sizes, int n_in,
                              void* d_out, int out_size)
{
    const float* nodes = (const float*)d_in[0];
    const float* pos   = (const float*)d_in[1];
    const float* rot   = (const float*)d_in[2];

    cudaFuncSetAttribute(attn_kernel, cudaFuncAttributeMaxDynamicSharedMemorySize, SMEM_DYN);

    proj_kq_kernel<<<SEQ/16, 256>>>(nodes, pos, rot,
        (const float*)d_in[3], (const float*)d_in[4],
        (const float*)d_in[5], (const float*)d_in[6], (const float*)d_in[7]);
    dim3 gv(SEQ/32, 3072/256);
    proj_val_kernel<<<gv, 256>>>(nodes, (const float*)d_in[8], (const float*)d_in[9]);
    pack_q_kernel<<<3072, 256>>>();
    pack_v_kernel<<<12288, 256>>>();
    dim3 ga(SEQ/128, NH);
    attn_kernel<<<ga, 256, SMEM_DYN>>>();
    reduce_kernel<<<(SEQ*ND)/256, 256>>>((float*)d_out);
}

// round 8
// speedup vs baseline: 3.1871x; 1.1441x over previous
#include <cuda_runtime.h>
#include <cuda_bf16.h>
#include <math.h>

#define SEQ 2048
#define ND  128
#define NH  24
#define NC  32
#define PI2 6.283185307179586f

typedef unsigned long long u64;
typedef unsigned int u32;

__device__ float g_k[NH*NC*SEQ];     // [h][c][i]
__device__ float g_q[NH*NC*SEQ];     // [h][c][j]
__device__ float g_v[NH*SEQ*ND];     // [h][j][d]
__device__ u64   g_qp[NH*64*512];    // packed bf16 q B-frags (hi 256 / lo 256 per chunk)
__device__ u64   g_vp[NH*64*2048];   // packed tf32 v frag-pairs
__device__ float g_part[NH*SEQ*ND];

__device__ __forceinline__ u32 tf32b(float f){ u32 r; asm("cvt.rna.tf32.f32 %0,%1;":"=r"(r):"f"(f)); return r; }
__device__ __forceinline__ u32 bf2(float lo, float hi){
    u32 r; asm("cvt.rn.bf16x2.f32 %0,%1,%2;" : "=r"(r) : "f"(hi), "f"(lo)); return r;
}

__device__ __forceinline__ void mma8(float* c, const u32* a, u32 b0, u32 b1){
    asm volatile("mma.sync.aligned.m16n8k8.row.col.f32.tf32.tf32.f32 "
        "{%0,%1,%2,%3},{%4,%5,%6,%7},{%8,%9},{%0,%1,%2,%3};"
        : "+f"(c[0]),"+f"(c[1]),"+f"(c[2]),"+f"(c[3])
        : "r"(a[0]),"r"(a[1]),"r"(a[2]),"r"(a[3]),"r"(b0),"r"(b1));
}
__device__ __forceinline__ void mma16b(float* c, const u32* a, u32 b0, u32 b1){
    asm volatile("mma.sync.aligned.m16n8k16.row.col.f32.bf16.bf16.f32 "
        "{%0,%1,%2,%3},{%4,%5,%6,%7},{%8,%9},{%0,%1,%2,%3};"
        : "+f"(c[0]),"+f"(c[1]),"+f"(c[2]),"+f"(c[3])
        : "r"(a[0]),"r"(a[1]),"r"(a[2]),"r"(a[3]),"r"(b0),"r"(b1));
}

__device__ __forceinline__ void cpa16(void* smem, const void* gmem){
    u32 s = (u32)__cvta_generic_to_shared(smem);
    asm volatile("cp.async.cg.shared.global [%0], [%1], 16;" :: "r"(s), "l"(gmem));
}
#define CP_COMMIT() asm volatile("cp.async.commit_group;")
#define CP_WAIT1()  asm volatile("cp.async.wait_group 1;")

__global__ __launch_bounds__(256) void proj_kq_kernel(
    const float* __restrict__ nodes, const float* __restrict__ pos,
    const float* __restrict__ rot,
    const float* __restrict__ w_nodes, const float* __restrict__ b_nodes,
    const float* __restrict__ w_pos, const float* __restrict__ b_pos,
    const float* __restrict__ w_rot)
{
    __shared__ float sn[16][128], sp[16][6], sr[16][4];
    const int i0 = blockIdx.x * 16, tid = threadIdx.x;
    for (int f = tid; f < 16*128; f += 256)
        sn[f>>7][f&127] = nodes[(i0+(f>>7))*128 + (f&127)];
    if (tid < 16) {
        int i = i0 + tid;
        float p0 = pos[i*3], p1 = pos[i*3+1], p2 = pos[i*3+2];
        sp[tid][0]=cosf(PI2*p0); sp[tid][1]=cosf(PI2*p1); sp[tid][2]=cosf(PI2*p2);
        sp[tid][3]=sinf(PI2*p0); sp[tid][4]=sinf(PI2*p1); sp[tid][5]=sinf(PI2*p2);
        sr[tid][0]=rot[i*4]; sr[tid][1]=rot[i*4+1]; sr[tid][2]=rot[i*4+2]; sr[tid][3]=rot[i*4+3];
    }
    __syncthreads();

    for (int o = tid; o < 512; o += 256) {
        float acc[16], b = b_nodes[o];
        #pragma unroll
        for (int r = 0; r < 16; r++) acc[r] = b;
        const float4* w4 = (const float4*)(w_nodes + o*128);
        for (int k4 = 0; k4 < 32; k4++) {
            float4 wv = __ldg(w4 + k4);
            #pragma unroll
            for (int r = 0; r < 16; r++)
                acc[r] += wv.x*sn[r][4*k4] + wv.y*sn[r][4*k4+1] + wv.z*sn[r][4*k4+2] + wv.w*sn[r][4*k4+3];
        }
        int hh = o>>6, cx = o&63;
        float* dst = ((cx<32)?g_k:g_q) + (hh*NC + (cx&31))*SEQ + i0;
        #pragma unroll
        for (int r4 = 0; r4 < 4; r4++)
            ((float4*)dst)[r4] = make_float4(acc[4*r4],acc[4*r4+1],acc[4*r4+2],acc[4*r4+3]);
    }
    for (int o = tid; o < 512; o += 256) {
        float acc[16], b = b_pos[o];
        #pragma unroll
        for (int r = 0; r < 16; r++) acc[r] = b;
        const float* w = w_pos + o*6;
        for (int kk = 0; kk < 6; kk++) {
            float wv = __ldg(w+kk);
            #pragma unroll
            for (int r = 0; r < 16; r++) acc[r] += wv * sp[r][kk];
        }
        int hh = (o>>6)+8, cx = o&63;
        float* dst = ((cx<32)?g_k:g_q) + (hh*NC + (cx&31))*SEQ + i0;
        #pragma unroll
        for (int r4 = 0; r4 < 4; r4++)
            ((float4*)dst)[r4] = make_float4(acc[4*r4],acc[4*r4+1],acc[4*r4+2],acc[4*r4+3]);
    }
    for (int o = tid; o < 512; o += 256) {
        float acc[16];
        #pragma unroll
        for (int r = 0; r < 16; r++) acc[r] = 0.f;
        const float* w = w_rot + o*4;
        for (int kk = 0; kk < 4; kk++) {
            float wv = __ldg(w+kk);
            #pragma unroll
            for (int r = 0; r < 16; r++) acc[r] += wv * sr[r][kk];
        }
        int hh = (o>>6)+16, cx = o&63;
        float* dst = ((cx<32)?g_k:g_q) + (hh*NC + (cx&31))*SEQ + i0;
        #pragma unroll
        for (int r4 = 0; r4 < 4; r4++)
            ((float4*)dst)[r4] = make_float4(acc[4*r4],acc[4*r4+1],acc[4*r4+2],acc[4*r4+3]);
    }
}

__global__ __launch_bounds__(256) void proj_val_kernel(
    const float* __restrict__ nodes,
    const float* __restrict__ w_values, const float* __restrict__ b_values)
{
    __shared__ float sa[32][128];
    __shared__ float sw[256][17];
    const int i0 = blockIdx.x*32, o0 = blockIdx.y*256, tid = threadIdx.x;
    const int g_i = tid>>5, g_o = tid&31;

    for (int f = tid; f < 32*128; f += 256)
        sa[f>>7][f&127] = nodes[(i0+(f>>7))*128 + (f&127)];

    float acc[4][8];
    #pragma unroll
    for (int e = 0; e < 8; e++) {
        float b = b_values[o0 + g_o + 32*e];
        #pragma unroll
        for (int r = 0; r < 4; r++) acc[r][e] = b;
    }
    for (int ks = 0; ks < 8; ks++) {
        __syncthreads();
        for (int f = tid; f < 256*16; f += 256)
            sw[f>>4][f&15] = w_values[(o0+(f>>4))*128 + ks*16 + (f&15)];
        __syncthreads();
        #pragma unroll 4
        for (int c = 0; c < 16; c++) {
            float a[4];
            #pragma unroll
            for (int r = 0; r < 4; r++) a[r] = sa[4*g_i+r][ks*16+c];
            #pragma unroll
            for (int e = 0; e < 8; e++) {
                float wv = sw[g_o+32*e][c];
                #pragma unroll
                for (int r = 0; r < 4; r++) acc[r][e] += a[r]*wv;
            }
        }
    }
    #pragma unroll
    for (int e = 0; e < 8; e++) {
        int o = o0 + g_o + 32*e, h = o>>7, dd = o&127;
        #pragma unroll
        for (int r = 0; r < 4; r++)
            g_v[((size_t)h*SEQ + i0+4*g_i+r)*ND + dd] = acc[r][e];
    }
}

// pack q into bf16 hi/lo m16n8k16 B-frags: per chunk 512 u64 (hi 0..255, lo 256..511)
__global__ __launch_bounds__(256) void pack_qb_kernel()
{
    int id = blockIdx.x*256 + threadIdx.x;          // 393216 total
    int lane = id&31, nt = (id>>5)&3, kt = (id>>7)&1, ch = (id>>8)&63, h = id>>14;
    int g = lane>>2, tig = lane&3;
    int c0 = kt*16 + 2*tig, j = ch*32 + nt*8 + g;
    float q00 = g_q[(h*NC+c0  )*SEQ + j];
    float q01 = g_q[(h*NC+c0+1)*SEQ + j];
    float q08 = g_q[(h*NC+c0+8)*SEQ + j];
    float q09 = g_q[(h*NC+c0+9)*SEQ + j];
    float h00 = __bfloat162float(__float2bfloat16_rn(q00));
    float h01 = __bfloat162float(__float2bfloat16_rn(q01));
    float h08 = __bfloat162float(__float2bfloat16_rn(q08));
    float h09 = __bfloat162float(__float2bfloat16_rn(q09));
    u32 hx = bf2(h00, h01), hy = bf2(h08, h09);
    u32 lx = bf2(q00-h00, q01-h01), ly = bf2(q08-h08, q09-h09);
    size_t base = ((size_t)h*64 + ch)*512 + kt*128 + nt*32 + lane;
    g_qp[base]       = ((u64)hy<<32) | hx;
    g_qp[base + 256] = ((u64)ly<<32) | lx;
}

__global__ __launch_bounds__(256) void pack_v_kernel()
{
    int id = blockIdx.x*256 + threadIdx.x;
    int l = id&31, nt = (id>>5)&15, kt = (id>>9)&3, ch = (id>>11)&63, h = id>>17;
    int j = ch*32 + kt*8 + (l&3), d = nt*8 + (l>>2);
    float v1 = g_v[((size_t)h*SEQ + j)*ND + d];
    float v2 = g_v[((size_t)h*SEQ + j+4)*ND + d];
    g_vp[id] = ((u64)tf32b(v2)<<32) | tf32b(v1);
}

// attention: 128 rows/block, 8 warps, cp.async double-buffer; QK bf16 3-pass, PV tf32
#define SMEM_DYN (2*4096 + 2*16384 + 8*2304)
__global__ __launch_bounds__(256) void attn_kernel()
{
    extern __shared__ __align__(16) unsigned char dsm[];
    u64* qbuf = (u64*)dsm;                 // 2 x 512 u64
    u64* vbuf = (u64*)(dsm + 8192);        // 2 x 2048 u64

    const int tid = threadIdx.x, w = tid>>5, lane = tid&31;
    const int g = lane>>2, tig = lane&3;
    const int h = blockIdx.y, i0 = blockIdx.x*128, iw = i0 + 16*w;
    u32* pP = (u32*)(dsm + 40960) + w*576; // [16][36] per warp

    // k A-fragments (m16k16 bf16), hi/lo split
    u32 ah[2][4], al[2][4];
    #pragma unroll
    for (int kt = 0; kt < 2; kt++) {
        int c0 = kt*16 + 2*tig;
        float kv[4][2];
        #pragma unroll
        for (int e = 0; e < 4; e++) {
            int c = c0 + (e>>1)*8;          // e=0,1: cols c0/c0+1; e=2,3: +8
            int i = iw + g + (e&1)*8;       // e even: row g; odd: row g+8
            kv[e][0] = g_k[(h*NC + c)*SEQ + i];
            kv[e][1] = g_k[(h*NC + c+1)*SEQ + i];
        }
        #pragma unroll
        for (int e = 0; e < 4; e++) {
            float h0 = __bfloat162float(__float2bfloat16_rn(kv[e][0]));
            float h1 = __bfloat162float(__float2bfloat16_rn(kv[e][1]));
            ah[kt][e] = bf2(h0, h1);
            al[kt][e] = bf2(kv[e][0]-h0, kv[e][1]-h1);
        }
    }

    float o[16][4];
    #pragma unroll
    for (int nt = 0; nt < 16; nt++) { o[nt][0]=0.f; o[nt][1]=0.f; o[nt][2]=0.f; o[nt][3]=0.f; }
    float m0 = -1e30f, m1 = -1e30f, s0 = 0.f, s1 = 0.f;

    const u64* gqp = g_qp + (size_t)h*64*512;
    const u64* gvp = g_vp + (size_t)h*64*2048;
    const bool sqh = (h >= 16);

    {   // prologue: chunk 0 -> buffer 0
        cpa16((float4*)qbuf + tid, (const float4*)gqp + tid);
        #pragma unroll
        for (int r = 0; r < 4; r++) cpa16((float4*)vbuf + tid + 256*r, (const float4*)gvp + tid + 256*r);
        CP_COMMIT();
    }

    for (int ch = 0; ch < 64; ch++) {
        int cur = ch & 1;
        if (ch < 63) {
            int nb = (ch+1) & 1;
            const float4* sq = (const float4*)(gqp + (size_t)(ch+1)*512);
            const float4* sv = (const float4*)(gvp + (size_t)(ch+1)*2048);
            cpa16((float4*)(qbuf + nb*512) + tid, sq + tid);
            #pragma unroll
            for (int r = 0; r < 4; r++) cpa16((float4*)(vbuf + nb*2048) + tid + 256*r, sv + tid + 256*r);
        }
        CP_COMMIT();
        CP_WAIT1();
        __syncthreads();

        const u64* sqp = qbuf + cur*512;
        const u64* svp = vbuf + cur*2048;

        // QK: bf16 3-pass (hh, lh, hl)
        float C[4][4];
        #pragma unroll
        for (int nt = 0; nt < 4; nt++) { C[nt][0]=0.f; C[nt][1]=0.f; C[nt][2]=0.f; C[nt][3]=0.f; }
        #pragma unroll
        for (int kt = 0; kt < 2; kt++) {
            #pragma unroll
            for (int nt = 0; nt < 4; nt++) {
                u64 bh = sqp[kt*128 + nt*32 + lane];
                u64 bl = sqp[256 + kt*128 + nt*32 + lane];
                u32 bh0 = (u32)bh, bh1 = (u32)(bh>>32);
                mma16b(C[nt], ah[kt], bh0, bh1);
                mma16b(C[nt], al[kt], bh0, bh1);
                mma16b(C[nt], ah[kt], (u32)bl, (u32)(bl>>32));
            }
        }
        if (sqh) {
            #pragma unroll
            for (int nt = 0; nt < 4; nt++) {
                C[nt][0]*=C[nt][0]; C[nt][1]*=C[nt][1]; C[nt][2]*=C[nt][2]; C[nt][3]*=C[nt][3];
            }
        }

        float cm0 = -1e30f, cm1 = -1e30f;
        #pragma unroll
        for (int nt = 0; nt < 4; nt++) {
            cm0 = fmaxf(cm0, fmaxf(C[nt][0], C[nt][1]));
            cm1 = fmaxf(cm1, fmaxf(C[nt][2], C[nt][3]));
        }
        cm0 = fmaxf(cm0, __shfl_xor_sync(0xffffffffu, cm0, 1));
        cm0 = fmaxf(cm0, __shfl_xor_sync(0xffffffffu, cm0, 2));
        cm1 = fmaxf(cm1, __shfl_xor_sync(0xffffffffu, cm1, 1));
        cm1 = fmaxf(cm1, __shfl_xor_sync(0xffffffffu, cm1, 2));
        float nm0 = fmaxf(m0, cm0), nm1 = fmaxf(m1, cm1);
        bool noup = (nm0 == m0) & (nm1 == m1);
        float ca0 = __expf(m0 - nm0), ca1 = __expf(m1 - nm1);
        m0 = nm0; m1 = nm1;

        float p[4][4];
        float cs0 = 0.f, cs1 = 0.f;
        #pragma unroll
        for (int nt = 0; nt < 4; nt++) {
            p[nt][0] = __expf(C[nt][0] - nm0);
            p[nt][1] = __expf(C[nt][1] - nm0);
            p[nt][2] = __expf(C[nt][2] - nm1);
            p[nt][3] = __expf(C[nt][3] - nm1);
            cs0 += p[nt][0] + p[nt][1];
            cs1 += p[nt][2] + p[nt][3];
        }
        cs0 += __shfl_xor_sync(0xffffffffu, cs0, 1);
        cs0 += __shfl_xor_sync(0xffffffffu, cs0, 2);
        cs1 += __shfl_xor_sync(0xffffffffu, cs1, 1);
        cs1 += __shfl_xor_sync(0xffffffffu, cs1, 2);
        s0 = s0*ca0 + cs0;
        s1 = s1*ca1 + cs1;
        if (!__all_sync(0xffffffffu, noup)) {
            #pragma unroll
            for (int nt = 0; nt < 16; nt++) {
                o[nt][0] *= ca0; o[nt][1] *= ca0;
                o[nt][2] *= ca1; o[nt][3] *= ca1;
            }
        }

        // P -> per-warp smem tile (tf32 bits), then A-fragments
        #pragma unroll
        for (int nt = 0; nt < 4; nt++) {
            u64 pr0 = ((u64)tf32b(p[nt][1])<<32) | tf32b(p[nt][0]);
            u64 pr1 = ((u64)tf32b(p[nt][3])<<32) | tf32b(p[nt][2]);
            *(u64*)&pP[g*36 + 8*nt + 2*tig]     = pr0;
            *(u64*)&pP[(g+8)*36 + 8*nt + 2*tig] = pr1;
        }
        __syncwarp();
        u32 pa[4][4];
        #pragma unroll
        for (int kt = 0; kt < 4; kt++) {
            pa[kt][0] = pP[g*36     + kt*8 + tig];
            pa[kt][1] = pP[(g+8)*36 + kt*8 + tig];
            pa[kt][2] = pP[g*36     + kt*8 + tig + 4];
            pa[kt][3] = pP[(g+8)*36 + kt*8 + tig + 4];
        }

        // PV (tf32)
        #pragma unroll
        for (int kt = 0; kt < 4; kt++) {
            #pragma unroll
            for (int nt = 0; nt < 16; nt++) {
                u64 bv = svp[kt*512 + nt*32 + lane];
                mma8(o[nt], pa[kt], (u32)bv, (u32)(bv>>32));
            }
        }
        __syncthreads();
    }

    float inv0 = 1.f/s0, inv1 = 1.f/s1;
    float* gp = g_part + ((size_t)h*SEQ + iw)*ND;
    #pragma unroll
    for (int nt = 0; nt < 16; nt++) {
        *(float2*)&gp[(size_t)g*ND + nt*8 + 2*tig]     = make_float2(o[nt][0]*inv0, o[nt][1]*inv0);
        *(float2*)&gp[(size_t)(g+8)*ND + nt*8 + 2*tig] = make_float2(o[nt][2]*inv1, o[nt][3]*inv1);
    }
}

__global__ __launch_bounds__(256) void reduce_kernel(float* __restrict__ out)
{
    int idx = blockIdx.x*256 + threadIdx.x;
    float s = 0.f;
    #pragma unroll
    for (int hh = 0; hh < NH; hh++) s += g_part[(size_t)hh*SEQ*ND + idx];
    out[idx] = s;
}

extern "C" void kernel_launch(void* const* d_in, const int* in_sizes, int n_in,
                              void* d_out, int out_size)
{
    const float* nodes = (const float*)d_in[0];
    const float* pos   = (const float*)d_in[1];
    const float* rot   = (const float*)d_in[2];

    cudaFuncSetAttribute(attn_kernel, cudaFuncAttributeMaxDynamicSharedMemorySize, SMEM_DYN);

    proj_kq_kernel<<<SEQ/16, 256>>>(nodes, pos, rot,
        (const float*)d_in[3], (const float*)d_in[4],
        (const float*)d_in[5], (const float*)d_in[6], (const float*)d_in[7]);
    dim3 gv(SEQ/32, 3072/256);
    proj_val_kernel<<<gv, 256>>>(nodes, (const float*)d_in[8], (const float*)d_in[9]);
    pack_qb_kernel<<<1536, 256>>>();
    pack_v_kernel<<<12288, 256>>>();
    dim3 ga(SEQ/128, NH);
    attn_kernel<<<ga, 256, SMEM_DYN>>>();
    reduce_kernel<<<(SEQ*ND)/256, 256>>>((float*)d_out);
}

// round 9
// speedup vs baseline: 4.1843x; 1.3129x over previous
#include <cuda_runtime.h>
#include <cuda_bf16.h>
#include <cuda_fp16.h>
#include <math.h>

#define SEQ 2048
#define ND  128
#define NH  24
#define NC  32
#define PI2 6.283185307179586f

typedef unsigned long long u64;
typedef unsigned int u32;

__device__ float g_k[NH*NC*SEQ];     // [h][c][i]
__device__ float g_q[NH*NC*SEQ];     // [h][c][j]
__device__ float g_v[NH*SEQ*ND];     // [h][j][d]
__device__ u64   g_qp[NH*64*512];    // bf16 q B-frags (hi 256 / lo 256 per chunk)
__device__ u64   g_vp[NH*64*1024];   // fp16 v B-frags (k16)
__device__ float g_part[NH*SEQ*ND];

__device__ __forceinline__ u32 bf2(float lo, float hi){
    u32 r; asm("cvt.rn.bf16x2.f32 %0,%1,%2;" : "=r"(r) : "f"(hi), "f"(lo)); return r;
}
__device__ __forceinline__ u32 hf2(float lo, float hi){
    __half2 h = __floats2half2_rn(lo, hi);
    return *(u32*)&h;
}

__device__ __forceinline__ void mma16b(float* c, const u32* a, u32 b0, u32 b1){
    asm volatile("mma.sync.aligned.m16n8k16.row.col.f32.bf16.bf16.f32 "
        "{%0,%1,%2,%3},{%4,%5,%6,%7},{%8,%9},{%0,%1,%2,%3};"
        : "+f"(c[0]),"+f"(c[1]),"+f"(c[2]),"+f"(c[3])
        : "r"(a[0]),"r"(a[1]),"r"(a[2]),"r"(a[3]),"r"(b0),"r"(b1));
}
__device__ __forceinline__ void mma16h(float* c, const u32* a, u32 b0, u32 b1){
    asm volatile("mma.sync.aligned.m16n8k16.row.col.f32.f16.f16.f32 "
        "{%0,%1,%2,%3},{%4,%5,%6,%7},{%8,%9},{%0,%1,%2,%3};"
        : "+f"(c[0]),"+f"(c[1]),"+f"(c[2]),"+f"(c[3])
        : "r"(a[0]),"r"(a[1]),"r"(a[2]),"r"(a[3]),"r"(b0),"r"(b1));
}

__device__ __forceinline__ void cpa16(void* smem, const void* gmem){
    u32 s = (u32)__cvta_generic_to_shared(smem);
    asm volatile("cp.async.cg.shared.global [%0], [%1], 16;" :: "r"(s), "l"(gmem));
}
#define CP_COMMIT() asm volatile("cp.async.commit_group;")
#define CP_WAIT1()  asm volatile("cp.async.wait_group 1;")

__global__ __launch_bounds__(256) void proj_kq_kernel(
    const float* __restrict__ nodes, const float* __restrict__ pos,
    const float* __restrict__ rot,
    const float* __restrict__ w_nodes, const float* __restrict__ b_nodes,
    const float* __restrict__ w_pos, const float* __restrict__ b_pos,
    const float* __restrict__ w_rot)
{
    __shared__ float sn[16][128], sp[16][6], sr[16][4];
    const int i0 = blockIdx.x * 16, tid = threadIdx.x;
    for (int f = tid; f < 16*128; f += 256)
        sn[f>>7][f&127] = nodes[(i0+(f>>7))*128 + (f&127)];
    if (tid < 16) {
        int i = i0 + tid;
        float p0 = pos[i*3], p1 = pos[i*3+1], p2 = pos[i*3+2];
        sp[tid][0]=cosf(PI2*p0); sp[tid][1]=cosf(PI2*p1); sp[tid][2]=cosf(PI2*p2);
        sp[tid][3]=sinf(PI2*p0); sp[tid][4]=sinf(PI2*p1); sp[tid][5]=sinf(PI2*p2);
        sr[tid][0]=rot[i*4]; sr[tid][1]=rot[i*4+1]; sr[tid][2]=rot[i*4+2]; sr[tid][3]=rot[i*4+3];
    }
    __syncthreads();

    for (int o = tid; o < 512; o += 256) {
        float acc[16], b = b_nodes[o];
        #pragma unroll
        for (int r = 0; r < 16; r++) acc[r] = b;
        const float4* w4 = (const float4*)(w_nodes + o*128);
        for (int k4 = 0; k4 < 32; k4++) {
            float4 wv = __ldg(w4 + k4);
            #pragma unroll
            for (int r = 0; r < 16; r++)
                acc[r] += wv.x*sn[r][4*k4] + wv.y*sn[r][4*k4+1] + wv.z*sn[r][4*k4+2] + wv.w*sn[r][4*k4+3];
        }
        int hh = o>>6, cx = o&63;
        float* dst = ((cx<32)?g_k:g_q) + (hh*NC + (cx&31))*SEQ + i0;
        #pragma unroll
        for (int r4 = 0; r4 < 4; r4++)
            ((float4*)dst)[r4] = make_float4(acc[4*r4],acc[4*r4+1],acc[4*r4+2],acc[4*r4+3]);
    }
    for (int o = tid; o < 512; o += 256) {
        float acc[16], b = b_pos[o];
        #pragma unroll
        for (int r = 0; r < 16; r++) acc[r] = b;
        const float* w = w_pos + o*6;
        for (int kk = 0; kk < 6; kk++) {
            float wv = __ldg(w+kk);
            #pragma unroll
            for (int r = 0; r < 16; r++) acc[r] += wv * sp[r][kk];
        }
        int hh = (o>>6)+8, cx = o&63;
        float* dst = ((cx<32)?g_k:g_q) + (hh*NC + (cx&31))*SEQ + i0;
        #pragma unroll
        for (int r4 = 0; r4 < 4; r4++)
            ((float4*)dst)[r4] = make_float4(acc[4*r4],acc[4*r4+1],acc[4*r4+2],acc[4*r4+3]);
    }
    for (int o = tid; o < 512; o += 256) {
        float acc[16];
        #pragma unroll
        for (int r = 0; r < 16; r++) acc[r] = 0.f;
        const float* w = w_rot + o*4;
        for (int kk = 0; kk < 4; kk++) {
            float wv = __ldg(w+kk);
            #pragma unroll
            for (int r = 0; r < 16; r++) acc[r] += wv * sr[r][kk];
        }
        int hh = (o>>6)+16, cx = o&63;
        float* dst = ((cx<32)?g_k:g_q) + (hh*NC + (cx&31))*SEQ + i0;
        #pragma unroll
        for (int r4 = 0; r4 < 4; r4++)
            ((float4*)dst)[r4] = make_float4(acc[4*r4],acc[4*r4+1],acc[4*r4+2],acc[4*r4+3]);
    }
}

__global__ __launch_bounds__(256) void proj_val_kernel(
    const float* __restrict__ nodes,
    const float* __restrict__ w_values, const float* __restrict__ b_values)
{
    __shared__ float sa[32][128];
    __shared__ float sw[256][17];
    const int i0 = blockIdx.x*32, o0 = blockIdx.y*256, tid = threadIdx.x;
    const int g_i = tid>>5, g_o = tid&31;

    for (int f = tid; f < 32*128; f += 256)
        sa[f>>7][f&127] = nodes[(i0+(f>>7))*128 + (f&127)];

    float acc[4][8];
    #pragma unroll
    for (int e = 0; e < 8; e++) {
        float b = b_values[o0 + g_o + 32*e];
        #pragma unroll
        for (int r = 0; r < 4; r++) acc[r][e] = b;
    }
    for (int ks = 0; ks < 8; ks++) {
        __syncthreads();
        for (int f = tid; f < 256*16; f += 256)
            sw[f>>4][f&15] = w_values[(o0+(f>>4))*128 + ks*16 + (f&15)];
        __syncthreads();
        #pragma unroll 4
        for (int c = 0; c < 16; c++) {
            float a[4];
            #pragma unroll
            for (int r = 0; r < 4; r++) a[r] = sa[4*g_i+r][ks*16+c];
            #pragma unroll
            for (int e = 0; e < 8; e++) {
                float wv = sw[g_o+32*e][c];
                #pragma unroll
                for (int r = 0; r < 4; r++) acc[r][e] += a[r]*wv;
            }
        }
    }
    #pragma unroll
    for (int e = 0; e < 8; e++) {
        int o = o0 + g_o + 32*e, h = o>>7, dd = o&127;
        #pragma unroll
        for (int r = 0; r < 4; r++)
            g_v[((size_t)h*SEQ + i0+4*g_i+r)*ND + dd] = acc[r][e];
    }
}

__global__ __launch_bounds__(256) void pack_qb_kernel()
{
    int id = blockIdx.x*256 + threadIdx.x;          // 393216 total
    int lane = id&31, nt = (id>>5)&3, kt = (id>>7)&1, ch = (id>>8)&63, h = id>>14;
    int g = lane>>2, tig = lane&3;
    int c0 = kt*16 + 2*tig, j = ch*32 + nt*8 + g;
    float q00 = g_q[(h*NC+c0  )*SEQ + j];
    float q01 = g_q[(h*NC+c0+1)*SEQ + j];
    float q08 = g_q[(h*NC+c0+8)*SEQ + j];
    float q09 = g_q[(h*NC+c0+9)*SEQ + j];
    float h00 = __bfloat162float(__float2bfloat16_rn(q00));
    float h01 = __bfloat162float(__float2bfloat16_rn(q01));
    float h08 = __bfloat162float(__float2bfloat16_rn(q08));
    float h09 = __bfloat162float(__float2bfloat16_rn(q09));
    u32 hx = bf2(h00, h01), hy = bf2(h08, h09);
    u32 lx = bf2(q00-h00, q01-h01), ly = bf2(q08-h08, q09-h09);
    size_t base = ((size_t)h*64 + ch)*512 + kt*128 + nt*32 + lane;
    g_qp[base]       = ((u64)hy<<32) | hx;
    g_qp[base + 256] = ((u64)ly<<32) | lx;
}

// pack v as fp16 m16n8k16 B-frags: per chunk 1024 u64 (kt in {0,1}: 16 j each)
__global__ __launch_bounds__(256) void pack_vh_kernel()
{
    int id = blockIdx.x*256 + threadIdx.x;          // 1572864 total
    int lane = id&31, nt = (id>>5)&15, kt = (id>>9)&1, ch = (id>>10)&63, h = id>>16;
    int g = lane>>2, tig = lane&3;
    int j0 = ch*32 + kt*16, d = nt*8 + g;
    const float* v = g_v + (size_t)h*SEQ*ND;
    u32 vx = hf2(v[(size_t)(j0+2*tig  )*ND + d], v[(size_t)(j0+2*tig+1)*ND + d]);
    u32 vy = hf2(v[(size_t)(j0+2*tig+8)*ND + d], v[(size_t)(j0+2*tig+9)*ND + d]);
    size_t base = ((size_t)h*64 + ch)*1024 + kt*512 + nt*32 + lane;
    g_vp[base] = ((u64)vy<<32) | vx;
}

// attention: 128 rows/block, 8 warps; QK bf16 3-pass, PV fp16 k16 single-pass
#define SMEM_DYN (2*4096 + 2*8192 + 8*1152)
__global__ __launch_bounds__(256) void attn_kernel()
{
    extern __shared__ __align__(16) unsigned char dsm[];
    u64* qbuf = (u64*)dsm;                 // 2 x 512 u64
    u64* vbuf = (u64*)(dsm + 8192);        // 2 x 1024 u64

    const int tid = threadIdx.x, w = tid>>5, lane = tid&31;
    const int g = lane>>2, tig = lane&3;
    const int h = blockIdx.y, i0 = blockIdx.x*128, iw = i0 + 16*w;
    u32* pP = (u32*)(dsm + 24576) + w*288; // [16][18] u32 (fp16x2 j-pairs) per warp

    // k A-fragments (m16k16 bf16), hi/lo split
    u32 ah[2][4], al[2][4];
    #pragma unroll
    for (int kt = 0; kt < 2; kt++) {
        int c0 = kt*16 + 2*tig;
        float kv[4][2];
        #pragma unroll
        for (int e = 0; e < 4; e++) {
            int c = c0 + (e>>1)*8;
            int i = iw + g + (e&1)*8;
            kv[e][0] = g_k[(h*NC + c)*SEQ + i];
            kv[e][1] = g_k[(h*NC + c+1)*SEQ + i];
        }
        #pragma unroll
        for (int e = 0; e < 4; e++) {
            float h0 = __bfloat162float(__float2bfloat16_rn(kv[e][0]));
            float h1 = __bfloat162float(__float2bfloat16_rn(kv[e][1]));
            ah[kt][e] = bf2(h0, h1);
            al[kt][e] = bf2(kv[e][0]-h0, kv[e][1]-h1);
        }
    }

    float o[16][4];
    #pragma unroll
    for (int nt = 0; nt < 16; nt++) { o[nt][0]=0.f; o[nt][1]=0.f; o[nt][2]=0.f; o[nt][3]=0.f; }
    float m0 = -1e30f, m1 = -1e30f, s0 = 0.f, s1 = 0.f;

    const u64* gqp = g_qp + (size_t)h*64*512;
    const u64* gvp = g_vp + (size_t)h*64*1024;
    const bool sqh = (h >= 16);

    {   // prologue: chunk 0 -> buffer 0
        cpa16((float4*)qbuf + tid, (const float4*)gqp + tid);
        #pragma unroll
        for (int r = 0; r < 2; r++) cpa16((float4*)vbuf + tid + 256*r, (const float4*)gvp + tid + 256*r);
        CP_COMMIT();
    }

    for (int ch = 0; ch < 64; ch++) {
        int cur = ch & 1;
        if (ch < 63) {
            int nb = (ch+1) & 1;
            const float4* sq = (const float4*)(gqp + (size_t)(ch+1)*512);
            const float4* sv = (const float4*)(gvp + (size_t)(ch+1)*1024);
            cpa16((float4*)(qbuf + nb*512) + tid, sq + tid);
            #pragma unroll
            for (int r = 0; r < 2; r++) cpa16((float4*)(vbuf + nb*1024) + tid + 256*r, sv + tid + 256*r);
        }
        CP_COMMIT();
        CP_WAIT1();
        __syncthreads();

        const u64* sqp = qbuf + cur*512;
        const u64* svp = vbuf + cur*1024;

        // QK: bf16 3-pass (hh, lh, hl)
        float C[4][4];
        #pragma unroll
        for (int nt = 0; nt < 4; nt++) { C[nt][0]=0.f; C[nt][1]=0.f; C[nt][2]=0.f; C[nt][3]=0.f; }
        #pragma unroll
        for (int kt = 0; kt < 2; kt++) {
            #pragma unroll
            for (int nt = 0; nt < 4; nt++) {
                u64 bh = sqp[kt*128 + nt*32 + lane];
                u64 bl = sqp[256 + kt*128 + nt*32 + lane];
                u32 bh0 = (u32)bh, bh1 = (u32)(bh>>32);
                mma16b(C[nt], ah[kt], bh0, bh1);
                mma16b(C[nt], al[kt], bh0, bh1);
                mma16b(C[nt], ah[kt], (u32)bl, (u32)(bl>>32));
            }
        }
        if (sqh) {
            #pragma unroll
            for (int nt = 0; nt < 4; nt++) {
                C[nt][0]*=C[nt][0]; C[nt][1]*=C[nt][1]; C[nt][2]*=C[nt][2]; C[nt][3]*=C[nt][3];
            }
        }

        float cm0 = -1e30f, cm1 = -1e30f;
        #pragma unroll
        for (int nt = 0; nt < 4; nt++) {
            cm0 = fmaxf(cm0, fmaxf(C[nt][0], C[nt][1]));
            cm1 = fmaxf(cm1, fmaxf(C[nt][2], C[nt][3]));
        }
        cm0 = fmaxf(cm0, __shfl_xor_sync(0xffffffffu, cm0, 1));
        cm0 = fmaxf(cm0, __shfl_xor_sync(0xffffffffu, cm0, 2));
        cm1 = fmaxf(cm1, __shfl_xor_sync(0xffffffffu, cm1, 1));
        cm1 = fmaxf(cm1, __shfl_xor_sync(0xffffffffu, cm1, 2));
        float nm0 = fmaxf(m0, cm0), nm1 = fmaxf(m1, cm1);
        bool noup = (nm0 == m0) & (nm1 == m1);
        float ca0 = __expf(m0 - nm0), ca1 = __expf(m1 - nm1);
        m0 = nm0; m1 = nm1;

        float p[4][4];
        float cs0 = 0.f, cs1 = 0.f;
        #pragma unroll
        for (int nt = 0; nt < 4; nt++) {
            p[nt][0] = __expf(C[nt][0] - nm0);
            p[nt][1] = __expf(C[nt][1] - nm0);
            p[nt][2] = __expf(C[nt][2] - nm1);
            p[nt][3] = __expf(C[nt][3] - nm1);
            cs0 += p[nt][0] + p[nt][1];
            cs1 += p[nt][2] + p[nt][3];
        }
        cs0 += __shfl_xor_sync(0xffffffffu, cs0, 1);
        cs0 += __shfl_xor_sync(0xffffffffu, cs0, 2);
        cs1 += __shfl_xor_sync(0xffffffffu, cs1, 1);
        cs1 += __shfl_xor_sync(0xffffffffu, cs1, 2);
        s0 = s0*ca0 + cs0;
        s1 = s1*ca1 + cs1;
        if (!__all_sync(0xffffffffu, noup)) {
            #pragma unroll
            for (int nt = 0; nt < 16; nt++) {
                o[nt][0] *= ca0; o[nt][1] *= ca0;
                o[nt][2] *= ca1; o[nt][3] *= ca1;
            }
        }

        // P -> per-warp smem tile (fp16x2 j-pairs), then k16 A-fragments
        #pragma unroll
        for (int nt = 0; nt < 4; nt++) {
            pP[g*18     + nt*4 + tig] = hf2(p[nt][0], p[nt][1]);
            pP[(g+8)*18 + nt*4 + tig] = hf2(p[nt][2], p[nt][3]);
        }
        __syncwarp();
        u32 pa[2][4];
        #pragma unroll
        for (int kt = 0; kt < 2; kt++) {
            pa[kt][0] = pP[g*18     + kt*8 + tig];
            pa[kt][1] = pP[(g+8)*18 + kt*8 + tig];
            pa[kt][2] = pP[g*18     + kt*8 + tig + 4];
            pa[kt][3] = pP[(g+8)*18 + kt*8 + tig + 4];
        }

        // PV: fp16 k16 single-pass
        #pragma unroll
        for (int kt = 0; kt < 2; kt++) {
            #pragma unroll
            for (int nt = 0; nt < 16; nt++) {
                u64 bv = svp[kt*512 + nt*32 + lane];
                mma16h(o[nt], pa[kt], (u32)bv, (u32)(bv>>32));
            }
        }
        __syncthreads();
    }

    float inv0 = 1.f/s0, inv1 = 1.f/s1;
    float* gp = g_part + ((size_t)h*SEQ + iw)*ND;
    #pragma unroll
    for (int nt = 0; nt < 16; nt++) {
        *(float2*)&gp[(size_t)g*ND + nt*8 + 2*tig]     = make_float2(o[nt][0]*inv0, o[nt][1]*inv0);
        *(float2*)&gp[(size_t)(g+8)*ND + nt*8 + 2*tig] = make_float2(o[nt][2]*inv1, o[nt][3]*inv1);
    }
}

__global__ __launch_bounds__(256) void reduce_kernel(float* __restrict__ out)
{
    int idx = blockIdx.x*256 + threadIdx.x;
    float s = 0.f;
    #pragma unroll
    for (int hh = 0; hh < NH; hh++) s += g_part[(size_t)hh*SEQ*ND + idx];
    out[idx] = s;
}

extern "C" void kernel_launch(void* const* d_in, const int* in_sizes, int n_in,
                              void* d_out, int out_size)
{
    const float* nodes = (const float*)d_in[0];
    const float* pos   = (const float*)d_in[1];
    const float* rot   = (const float*)d_in[2];

    cudaFuncSetAttribute(attn_kernel, cudaFuncAttributeMaxDynamicSharedMemorySize, SMEM_DYN);

    proj_kq_kernel<<<SEQ/16, 256>>>(nodes, pos, rot,
        (const float*)d_in[3], (const float*)d_in[4],
        (const float*)d_in[5], (const float*)d_in[6], (const float*)d_in[7]);
    dim3 gv(SEQ/32, 3072/256);
    proj_val_kernel<<<gv, 256>>>(nodes, (const float*)d_in[8], (const float*)d_in[9]);
    pack_qb_kernel<<<1536, 256>>>();
    pack_vh_kernel<<<6144, 256>>>();
    dim3 ga(SEQ/128, NH);
    attn_kernel<<<ga, 256, SMEM_DYN>>>();
    reduce_kernel<<<(SEQ*ND)/256, 256>>>((float*)d_out);
}

// round 10
// speedup vs baseline: 5.0641x; 1.2103x over previous
#include <cuda_runtime.h>
#include <cuda_bf16.h>
#include <cuda_fp16.h>
#include <math.h>

#define SEQ 2048
#define ND  128
#define NH  24
#define NC  32
#define PI2 6.283185307179586f

typedef unsigned long long u64;
typedef unsigned int u32;

__device__ float g_k[NH*NC*SEQ];     // [h][c][i]
__device__ float g_q[NH*NC*SEQ];     // [h][c][j]
__device__ u64   g_qp[NH*64*512];    // bf16 q B-frags (hi 256 / lo 256 per chunk)
__device__ u64   g_vp[NH*64*1024];   // fp16 v B-frags (k16)
__device__ u64   g_na[128*8*4*32];   // nodes bf16 hi/lo A-frags [jt][kt][s][lane]
__device__ u64   g_wb[384*8*2*32];   // w_values bf16 hi/lo B-frags [nt][kt][s][lane]
__device__ float g_part[NH*SEQ*ND];

__device__ __forceinline__ u32 bf2(float lo, float hi){
    u32 r; asm("cvt.rn.bf16x2.f32 %0,%1,%2;" : "=r"(r) : "f"(hi), "f"(lo)); return r;
}
__device__ __forceinline__ u32 hf2(float lo, float hi){
    __half2 h = __floats2half2_rn(lo, hi);
    return *(u32*)&h;
}
__device__ __forceinline__ float bfr(float x){ return __bfloat162float(__float2bfloat16_rn(x)); }

__device__ __forceinline__ void mma16b(float* c, const u32* a, u32 b0, u32 b1){
    asm volatile("mma.sync.aligned.m16n8k16.row.col.f32.bf16.bf16.f32 "
        "{%0,%1,%2,%3},{%4,%5,%6,%7},{%8,%9},{%0,%1,%2,%3};"
        : "+f"(c[0]),"+f"(c[1]),"+f"(c[2]),"+f"(c[3])
        : "r"(a[0]),"r"(a[1]),"r"(a[2]),"r"(a[3]),"r"(b0),"r"(b1));
}
__device__ __forceinline__ void mma16h(float* c, const u32* a, u32 b0, u32 b1){
    asm volatile("mma.sync.aligned.m16n8k16.row.col.f32.f16.f16.f32 "
        "{%0,%1,%2,%3},{%4,%5,%6,%7},{%8,%9},{%0,%1,%2,%3};"
        : "+f"(c[0]),"+f"(c[1]),"+f"(c[2]),"+f"(c[3])
        : "r"(a[0]),"r"(a[1]),"r"(a[2]),"r"(a[3]),"r"(b0),"r"(b1));
}

__device__ __forceinline__ void cpa16(void* smem, const void* gmem){
    u32 s = (u32)__cvta_generic_to_shared(smem);
    asm volatile("cp.async.cg.shared.global [%0], [%1], 16;" :: "r"(s), "l"(gmem));
}
#define CP_COMMIT() asm volatile("cp.async.commit_group;")
#define CP_WAIT1()  asm volatile("cp.async.wait_group 1;")
#define CP_WAIT0()  asm volatile("cp.async.wait_group 0;")

__global__ __launch_bounds__(256) void proj_kq_kernel(
    const float* __restrict__ nodes, const float* __restrict__ pos,
    const float* __restrict__ rot,
    const float* __restrict__ w_nodes, const float* __restrict__ b_nodes,
    const float* __restrict__ w_pos, const float* __restrict__ b_pos,
    const float* __restrict__ w_rot)
{
    __shared__ float sn[16][128], sp[16][6], sr[16][4];
    const int i0 = blockIdx.x * 16, tid = threadIdx.x;
    for (int f = tid; f < 16*128; f += 256)
        sn[f>>7][f&127] = nodes[(i0+(f>>7))*128 + (f&127)];
    if (tid < 16) {
        int i = i0 + tid;
        float p0 = pos[i*3], p1 = pos[i*3+1], p2 = pos[i*3+2];
        sp[tid][0]=cosf(PI2*p0); sp[tid][1]=cosf(PI2*p1); sp[tid][2]=cosf(PI2*p2);
        sp[tid][3]=sinf(PI2*p0); sp[tid][4]=sinf(PI2*p1); sp[tid][5]=sinf(PI2*p2);
        sr[tid][0]=rot[i*4]; sr[tid][1]=rot[i*4+1]; sr[tid][2]=rot[i*4+2]; sr[tid][3]=rot[i*4+3];
    }
    __syncthreads();

    for (int o = tid; o < 512; o += 256) {
        float acc[16], b = b_nodes[o];
        #pragma unroll
        for (int r = 0; r < 16; r++) acc[r] = b;
        const float4* w4 = (const float4*)(w_nodes + o*128);
        for (int k4 = 0; k4 < 32; k4++) {
            float4 wv = __ldg(w4 + k4);
            #pragma unroll
            for (int r = 0; r < 16; r++)
                acc[r] += wv.x*sn[r][4*k4] + wv.y*sn[r][4*k4+1] + wv.z*sn[r][4*k4+2] + wv.w*sn[r][4*k4+3];
        }
        int hh = o>>6, cx = o&63;
        float* dst = ((cx<32)?g_k:g_q) + (hh*NC + (cx&31))*SEQ + i0;
        #pragma unroll
        for (int r4 = 0; r4 < 4; r4++)
            ((float4*)dst)[r4] = make_float4(acc[4*r4],acc[4*r4+1],acc[4*r4+2],acc[4*r4+3]);
    }
    for (int o = tid; o < 512; o += 256) {
        float acc[16], b = b_pos[o];
        #pragma unroll
        for (int r = 0; r < 16; r++) acc[r] = b;
        const float* w = w_pos + o*6;
        for (int kk = 0; kk < 6; kk++) {
            float wv = __ldg(w+kk);
            #pragma unroll
            for (int r = 0; r < 16; r++) acc[r] += wv * sp[r][kk];
        }
        int hh = (o>>6)+8, cx = o&63;
        float* dst = ((cx<32)?g_k:g_q) + (hh*NC + (cx&31))*SEQ + i0;
        #pragma unroll
        for (int r4 = 0; r4 < 4; r4++)
            ((float4*)dst)[r4] = make_float4(acc[4*r4],acc[4*r4+1],acc[4*r4+2],acc[4*r4+3]);
    }
    for (int o = tid; o < 512; o += 256) {
        float acc[16];
        #pragma unroll
        for (int r = 0; r < 16; r++) acc[r] = 0.f;
        const float* w = w_rot + o*4;
        for (int kk = 0; kk < 4; kk++) {
            float wv = __ldg(w+kk);
            #pragma unroll
            for (int r = 0; r < 16; r++) acc[r] += wv * sr[r][kk];
        }
        int hh = (o>>6)+16, cx = o&63;
        float* dst = ((cx<32)?g_k:g_q) + (hh*NC + (cx&31))*SEQ + i0;
        #pragma unroll
        for (int r4 = 0; r4 < 4; r4++)
            ((float4*)dst)[r4] = make_float4(acc[4*r4],acc[4*r4+1],acc[4*r4+2],acc[4*r4+3]);
    }
}

// pack nodes into bf16 hi/lo m16k16 A-frags
__global__ __launch_bounds__(256) void pack_nodes_kernel(const float* __restrict__ nodes)
{
    int id = blockIdx.x*256 + threadIdx.x;   // 32768: (jt 128)(kt 8)(lane 32)
    int lane = id&31, kt = (id>>5)&7, jt = id>>8;
    int g = lane>>2, tig = lane&3;
    int r0 = jt*16+g, c0 = kt*16+2*tig;
    float2 v00 = *(const float2*)&nodes[r0*128 + c0];       // a0: row g,   k c0,c0+1
    float2 v10 = *(const float2*)&nodes[(r0+8)*128 + c0];   // a1: row g+8
    float2 v01 = *(const float2*)&nodes[r0*128 + c0+8];     // a2: row g,   k c0+8,+9
    float2 v11 = *(const float2*)&nodes[(r0+8)*128 + c0+8]; // a3: row g+8
    float h00=bfr(v00.x), h01=bfr(v00.y), h10=bfr(v10.x), h11=bfr(v10.y);
    float h20=bfr(v01.x), h21=bfr(v01.y), h30=bfr(v11.x), h31=bfr(v11.y);
    u64 hi01 = ((u64)bf2(h10,h11)<<32) | bf2(h00,h01);
    u64 hi23 = ((u64)bf2(h30,h31)<<32) | bf2(h20,h21);
    u64 lo01 = ((u64)bf2(v10.x-h10,v10.y-h11)<<32) | bf2(v00.x-h00,v00.y-h01);
    u64 lo23 = ((u64)bf2(v11.x-h30,v11.y-h31)<<32) | bf2(v01.x-h20,v01.y-h21);
    size_t base = (size_t)(jt*8+kt)*4*32 + lane;
    g_na[base]      = hi01;
    g_na[base+32]   = hi23;
    g_na[base+64]   = lo01;
    g_na[base+96]   = lo23;
}

// pack w_values into bf16 hi/lo m16n8k16 B-frags
__global__ __launch_bounds__(256) void pack_w_kernel(const float* __restrict__ w)
{
    int id = blockIdx.x*256 + threadIdx.x;   // 98304: (nt 384)(kt 8)(lane)
    int lane = id&31, kt = (id>>5)&7, nt = id>>8;
    int g = lane>>2, tig = lane&3;
    int o = nt*8+g, c0 = kt*16+2*tig;
    float2 wa = *(const float2*)&w[o*128 + c0];
    float2 wb = *(const float2*)&w[o*128 + c0+8];
    float ha0=bfr(wa.x), ha1=bfr(wa.y), hb0=bfr(wb.x), hb1=bfr(wb.y);
    u64 hi = ((u64)bf2(hb0,hb1)<<32) | bf2(ha0,ha1);
    u64 lo = ((u64)bf2(wb.x-hb0,wb.y-hb1)<<32) | bf2(wa.x-ha0,wa.y-ha1);
    size_t base = (size_t)(nt*8+kt)*2*32 + lane;
    g_wb[base]    = hi;
    g_wb[base+32] = lo;
}

// values projection as 3-pass split-bf16 mma GEMM, writing g_vp frags directly
// block = (jb: 32 j-rows = one chunk, h: 128 d = one head)
#define PV_SMEM (16384 + 65536 + 8448)
__global__ __launch_bounds__(256) void proj_val_mma(const float* __restrict__ b_values)
{
    extern __shared__ __align__(16) unsigned char sm[];
    u64* sA = (u64*)sm;                    // [2 jt][8 kt][4 s][32]
    u64* sB = (u64*)(sm + 16384);          // [16 nt][8 kt][2 s][32]
    __half* sO = (__half*)(sm + 81920);    // [32 j][132]

    const int tid = threadIdx.x, w = tid>>5, lane = tid&31;
    const int g = lane>>2, tig = lane&3;
    const int jb = blockIdx.x, h = blockIdx.y;
    const int jw = w>>2, dw = w&3;

    const float4* srcA = (const float4*)(g_na + (size_t)(jb*2)*8*4*32);
    for (int f = tid; f < 1024; f += 256) cpa16((float4*)sA + f, srcA + f);
    const float4* srcB = (const float4*)(g_wb + (size_t)h*16*8*2*32);
    for (int f = tid; f < 4096; f += 256) cpa16((float4*)sB + f, srcB + f);
    CP_COMMIT();
    CP_WAIT0();
    __syncthreads();

    float acc[4][4];
    #pragma unroll
    for (int nt = 0; nt < 4; nt++) { acc[nt][0]=0.f; acc[nt][1]=0.f; acc[nt][2]=0.f; acc[nt][3]=0.f; }

    const u64* A = sA + (size_t)jw*(8*4*32);
    const u64* B = sB + (size_t)dw*4*(8*2*32);
    #pragma unroll
    for (int kt = 0; kt < 8; kt++) {
        u64 h01 = A[(kt*4+0)*32+lane], h23 = A[(kt*4+1)*32+lane];
        u64 l01 = A[(kt*4+2)*32+lane], l23 = A[(kt*4+3)*32+lane];
        u32 ah[4] = {(u32)h01,(u32)(h01>>32),(u32)h23,(u32)(h23>>32)};
        u32 al[4] = {(u32)l01,(u32)(l01>>32),(u32)l23,(u32)(l23>>32)};
        #pragma unroll
        for (int nt = 0; nt < 4; nt++) {
            u64 bh = B[((nt*8+kt)*2+0)*32+lane];
            u64 bl = B[((nt*8+kt)*2+1)*32+lane];
            mma16b(acc[nt], ah, (u32)bh, (u32)(bh>>32));
            mma16b(acc[nt], al, (u32)bh, (u32)(bh>>32));
            mma16b(acc[nt], ah, (u32)bl, (u32)(bl>>32));
        }
    }

    // bias + fp16 round into smem out-tile
    #pragma unroll
    for (int nt = 0; nt < 4; nt++) {
        int d = dw*32 + nt*8 + 2*tig;
        float b0 = __ldg(&b_values[h*128 + d]);
        float b1 = __ldg(&b_values[h*128 + d + 1]);
        int j0 = jw*16 + g;
        *(__half2*)&sO[j0*132 + d]     = __floats2half2_rn(acc[nt][0]+b0, acc[nt][1]+b1);
        *(__half2*)&sO[(j0+8)*132 + d] = __floats2half2_rn(acc[nt][2]+b0, acc[nt][3]+b1);
    }
    __syncthreads();

    // pack v-frags (layout identical to old pack_vh): f = kt*512 + nt*32 + lane
    u64* dst = g_vp + ((size_t)h*64 + jb)*1024;
    #pragma unroll
    for (int q = 0; q < 4; q++) {
        int f = tid*4 + q;
        int lv = f&31, ntv = (f>>5)&15, ktv = f>>9;
        int gv = lv>>2, tv = lv&3;
        int d = ntv*8 + gv, j = ktv*16;
        __half2 x = __halves2half2(sO[(j+2*tv)*132+d],   sO[(j+2*tv+1)*132+d]);
        __half2 y = __halves2half2(sO[(j+2*tv+8)*132+d], sO[(j+2*tv+9)*132+d]);
        dst[f] = ((u64)(*(u32*)&y)<<32) | (*(u32*)&x);
    }
}

__global__ __launch_bounds__(256) void pack_qb_kernel()
{
    int id = blockIdx.x*256 + threadIdx.x;          // 393216 total
    int lane = id&31, nt = (id>>5)&3, kt = (id>>7)&1, ch = (id>>8)&63, h = id>>14;
    int g = lane>>2, tig = lane&3;
    int c0 = kt*16 + 2*tig, j = ch*32 + nt*8 + g;
    float q00 = g_q[(h*NC+c0  )*SEQ + j];
    float q01 = g_q[(h*NC+c0+1)*SEQ + j];
    float q08 = g_q[(h*NC+c0+8)*SEQ + j];
    float q09 = g_q[(h*NC+c0+9)*SEQ + j];
    float h00 = bfr(q00), h01 = bfr(q01), h08 = bfr(q08), h09 = bfr(q09);
    u32 hx = bf2(h00, h01), hy = bf2(h08, h09);
    u32 lx = bf2(q00-h00, q01-h01), ly = bf2(q08-h08, q09-h09);
    size_t base = ((size_t)h*64 + ch)*512 + kt*128 + nt*32 + lane;
    g_qp[base]       = ((u64)hy<<32) | hx;
    g_qp[base + 256] = ((u64)ly<<32) | lx;
}

// attention: 128 rows/block, 8 warps; QK bf16 3-pass, PV fp16 k16 single-pass
#define SMEM_DYN (2*4096 + 2*8192 + 8*1152)
__global__ __launch_bounds__(256) void attn_kernel()
{
    extern __shared__ __align__(16) unsigned char dsm[];
    u64* qbuf = (u64*)dsm;                 // 2 x 512 u64
    u64* vbuf = (u64*)(dsm + 8192);        // 2 x 1024 u64

    const int tid = threadIdx.x, w = tid>>5, lane = tid&31;
    const int g = lane>>2, tig = lane&3;
    const int h = blockIdx.y, i0 = blockIdx.x*128, iw = i0 + 16*w;
    u32* pP = (u32*)(dsm + 24576) + w*288; // [16][18] u32 per warp

    u32 ah[2][4], al[2][4];
    #pragma unroll
    for (int kt = 0; kt < 2; kt++) {
        int c0 = kt*16 + 2*tig;
        float kv[4][2];
        #pragma unroll
        for (int e = 0; e < 4; e++) {
            int c = c0 + (e>>1)*8;
            int i = iw + g + (e&1)*8;
            kv[e][0] = g_k[(h*NC + c)*SEQ + i];
            kv[e][1] = g_k[(h*NC + c+1)*SEQ + i];
        }
        #pragma unroll
        for (int e = 0; e < 4; e++) {
            float h0 = bfr(kv[e][0]);
            float h1 = bfr(kv[e][1]);
            ah[kt][e] = bf2(h0, h1);
            al[kt][e] = bf2(kv[e][0]-h0, kv[e][1]-h1);
        }
    }

    float o[16][4];
    #pragma unroll
    for (int nt = 0; nt < 16; nt++) { o[nt][0]=0.f; o[nt][1]=0.f; o[nt][2]=0.f; o[nt][3]=0.f; }
    float m0 = -1e30f, m1 = -1e30f, s0 = 0.f, s1 = 0.f;

    const u64* gqp = g_qp + (size_t)h*64*512;
    const u64* gvp = g_vp + (size_t)h*64*1024;
    const bool sqh = (h >= 16);

    {
        cpa16((float4*)qbuf + tid, (const float4*)gqp + tid);
        #pragma unroll
        for (int r = 0; r < 2; r++) cpa16((float4*)vbuf + tid + 256*r, (const float4*)gvp + tid + 256*r);
        CP_COMMIT();
    }

    for (int ch = 0; ch < 64; ch++) {
        int cur = ch & 1;
        if (ch < 63) {
            int nb = (ch+1) & 1;
            const float4* sq = (const float4*)(gqp + (size_t)(ch+1)*512);
            const float4* sv = (const float4*)(gvp + (size_t)(ch+1)*1024);
            cpa16((float4*)(qbuf + nb*512) + tid, sq + tid);
            #pragma unroll
            for (int r = 0; r < 2; r++) cpa16((float4*)(vbuf + nb*1024) + tid + 256*r, sv + tid + 256*r);
        }
        CP_COMMIT();
        CP_WAIT1();
        __syncthreads();

        const u64* sqp = qbuf + cur*512;
        const u64* svp = vbuf + cur*1024;

        float C[4][4];
        #pragma unroll
        for (int nt = 0; nt < 4; nt++) { C[nt][0]=0.f; C[nt][1]=0.f; C[nt][2]=0.f; C[nt][3]=0.f; }
        #pragma unroll
        for (int kt = 0; kt < 2; kt++) {
            #pragma unroll
            for (int nt = 0; nt < 4; nt++) {
                u64 bh = sqp[kt*128 + nt*32 + lane];
                u64 bl = sqp[256 + kt*128 + nt*32 + lane];
                u32 bh0 = (u32)bh, bh1 = (u32)(bh>>32);
                mma16b(C[nt], ah[kt], bh0, bh1);
                mma16b(C[nt], al[kt], bh0, bh1);
                mma16b(C[nt], ah[kt], (u32)bl, (u32)(bl>>32));
            }
        }
        if (sqh) {
            #pragma unroll
            for (int nt = 0; nt < 4; nt++) {
                C[nt][0]*=C[nt][0]; C[nt][1]*=C[nt][1]; C[nt][2]*=C[nt][2]; C[nt][3]*=C[nt][3];
            }
        }

        float cm0 = -1e30f, cm1 = -1e30f;
        #pragma unroll
        for (int nt = 0; nt < 4; nt++) {
            cm0 = fmaxf(cm0, fmaxf(C[nt][0], C[nt][1]));
            cm1 = fmaxf(cm1, fmaxf(C[nt][2], C[nt][3]));
        }
        cm0 = fmaxf(cm0, __shfl_xor_sync(0xffffffffu, cm0, 1));
        cm0 = fmaxf(cm0, __shfl_xor_sync(0xffffffffu, cm0, 2));
        cm1 = fmaxf(cm1, __shfl_xor_sync(0xffffffffu, cm1, 1));
        cm1 = fmaxf(cm1, __shfl_xor_sync(0xffffffffu, cm1, 2));
        float nm0 = fmaxf(m0, cm0), nm1 = fmaxf(m1, cm1);
        bool noup = (nm0 == m0) & (nm1 == m1);
        float ca0 = __expf(m0 - nm0), ca1 = __expf(m1 - nm1);
        m0 = nm0; m1 = nm1;

        float p[4][4];
        float cs0 = 0.f, cs1 = 0.f;
        #pragma unroll
        for (int nt = 0; nt < 4; nt++) {
            p[nt][0] = __expf(C[nt][0] - nm0);
            p[nt][1] = __expf(C[nt][1] - nm0);
            p[nt][2] = __expf(C[nt][2] - nm1);
            p[nt][3] = __expf(C[nt][3] - nm1);
            cs0 += p[nt][0] + p[nt][1];
            cs1 += p[nt][2] + p[nt][3];
        }
        cs0 += __shfl_xor_sync(0xffffffffu, cs0, 1);
        cs0 += __shfl_xor_sync(0xffffffffu, cs0, 2);
        cs1 += __shfl_xor_sync(0xffffffffu, cs1, 1);
        cs1 += __shfl_xor_sync(0xffffffffu, cs1, 2);
        s0 = s0*ca0 + cs0;
        s1 = s1*ca1 + cs1;
        if (!__all_sync(0xffffffffu, noup)) {
            #pragma unroll
            for (int nt = 0; nt < 16; nt++) {
                o[nt][0] *= ca0; o[nt][1] *= ca0;
                o[nt][2] *= ca1; o[nt][3] *= ca1;
            }
        }

        #pragma unroll
        for (int nt = 0; nt < 4; nt++) {
            pP[g*18     + nt*4 + tig] = hf2(p[nt][0], p[nt][1]);
            pP[(g+8)*18 + nt*4 + tig] = hf2(p[nt][2], p[nt][3]);
        }
        __syncwarp();
        u32 pa[2][4];
        #pragma unroll
        for (int kt = 0; kt < 2; kt++) {
            pa[kt][0] = pP[g*18     + kt*8 + tig];
            pa[kt][1] = pP[(g+8)*18 + kt*8 + tig];
            pa[kt][2] = pP[g*18     + kt*8 + tig + 4];
            pa[kt][3] = pP[(g+8)*18 + kt*8 + tig + 4];
        }

        #pragma unroll
        for (int kt = 0; kt < 2; kt++) {
            #pragma unroll
            for (int nt = 0; nt < 16; nt++) {
                u64 bv = svp[kt*512 + nt*32 + lane];
                mma16h(o[nt], pa[kt], (u32)bv, (u32)(bv>>32));
            }
        }
        __syncthreads();
    }

    float inv0 = 1.f/s0, inv1 = 1.f/s1;
    float* gp = g_part + ((size_t)h*SEQ + iw)*ND;
    #pragma unroll
    for (int nt = 0; nt < 16; nt++) {
        *(float2*)&gp[(size_t)g*ND + nt*8 + 2*tig]     = make_float2(o[nt][0]*inv0, o[nt][1]*inv0);
        *(float2*)&gp[(size_t)(g+8)*ND + nt*8 + 2*tig] = make_float2(o[nt][2]*inv1, o[nt][3]*inv1);
    }
}

__global__ __launch_bounds__(256) void reduce_kernel(float* __restrict__ out)
{
    int idx = blockIdx.x*256 + threadIdx.x;
    float s = 0.f;
    #pragma unroll
    for (int hh = 0; hh < NH; hh++) s += g_part[(size_t)hh*SEQ*ND + idx];
    out[idx] = s;
}

extern "C" void kernel_launch(void* const* d_in, const int* in_sizes, int n_in,
                              void* d_out, int out_size)
{
    const float* nodes = (const float*)d_in[0];
    const float* pos   = (const float*)d_in[1];
    const float* rot   = (const float*)d_in[2];

    cudaFuncSetAttribute(attn_kernel, cudaFuncAttributeMaxDynamicSharedMemorySize, SMEM_DYN);
    cudaFuncSetAttribute(proj_val_mma, cudaFuncAttributeMaxDynamicSharedMemorySize, PV_SMEM);

    pack_nodes_kernel<<<128, 256>>>(nodes);
    pack_w_kernel<<<384, 256>>>((const float*)d_in[8]);
    proj_kq_kernel<<<SEQ/16, 256>>>(nodes, pos, rot,
        (const float*)d_in[3], (const float*)d_in[4],
        (const float*)d_in[5], (const float*)d_in[6], (const float*)d_in[7]);
    pack_qb_kernel<<<1536, 256>>>();
    dim3 gpv(64, NH);
    proj_val_mma<<<gpv, 256, PV_SMEM>>>((const float*)d_in[9]);
    dim3 ga(SEQ/128, NH);
    attn_kernel<<<ga, 256, SMEM_DYN>>>();
    reduce_kernel<<<(SEQ*ND)/256, 256>>>((float*)d_out);
}

// round 14
// speedup vs baseline: 5.5605x; 1.0980x over previous
#include <cuda_runtime.h>
#include <cuda_bf16.h>
#include <cuda_fp16.h>
#include <math.h>

#define SEQ 2048
#define ND  128
#define NH  24
#define NC  32
#define PI2 6.283185307179586f

typedef unsigned long long u64;
typedef unsigned int u32;

__device__ float  g_k[NH*NC*SEQ];     // [h][c][i]
__device__ float  g_q[NH*NC*SEQ];     // [h][c][j]
__device__ u64    g_qp[NH*64*512];    // bf16 q B-frags (hi 256 / lo 256 per chunk)
__device__ u64    g_vp[NH*64*1024];   // fp16 v B-frags (k16)
__device__ u64    g_na[128*8*4*32];   // nodes bf16 hi/lo A-frags
__device__ u64    g_wb[384*8*2*32];   // w_values bf16 hi/lo B-frags
__device__ u64    g_wkq[64*8*2*32];   // w_nodes_kq bf16 hi/lo B-frags
__device__ __half g_part[NH*SEQ*ND];  // fp16 per-head partials

__device__ __forceinline__ u32 bf2(float lo, float hi){
    u32 r; asm("cvt.rn.bf16x2.f32 %0,%1,%2;" : "=r"(r) : "f"(hi), "f"(lo)); return r;
}
__device__ __forceinline__ u32 hf2(float lo, float hi){
    __half2 h = __floats2half2_rn(lo, hi);
    return *(u32*)&h;
}
__device__ __forceinline__ float bfr(float x){ return __bfloat162float(__float2bfloat16_rn(x)); }

__device__ __forceinline__ void mma16b(float* c, const u32* a, u32 b0, u32 b1){
    asm volatile("mma.sync.aligned.m16n8k16.row.col.f32.bf16.bf16.f32 "
        "{%0,%1,%2,%3},{%4,%5,%6,%7},{%8,%9},{%0,%1,%2,%3};"
        : "+f"(c[0]),"+f"(c[1]),"+f"(c[2]),"+f"(c[3])
        : "r"(a[0]),"r"(a[1]),"r"(a[2]),"r"(a[3]),"r"(b0),"r"(b1));
}
__device__ __forceinline__ void mma16h(float* c, const u32* a, u32 b0, u32 b1){
    asm volatile("mma.sync.aligned.m16n8k16.row.col.f32.f16.f16.f32 "
        "{%0,%1,%2,%3},{%4,%5,%6,%7},{%8,%9},{%0,%1,%2,%3};"
        : "+f"(c[0]),"+f"(c[1]),"+f"(c[2]),"+f"(c[3])
        : "r"(a[0]),"r"(a[1]),"r"(a[2]),"r"(a[3]),"r"(b0),"r"(b1));
}

__device__ __forceinline__ void cpa16(void* smem, const void* gmem){
    u32 s = (u32)__cvta_generic_to_shared(smem);
    asm volatile("cp.async.cg.shared.global [%0], [%1], 16;" :: "r"(s), "l"(gmem));
}
#define CP_COMMIT() asm volatile("cp.async.commit_group;")
#define CP_WAIT1()  asm volatile("cp.async.wait_group 1;")
#define CP_WAIT0()  asm volatile("cp.async.wait_group 0;")

// ---- pos/rot k-q projections (heads 8..23) — scalar, tiny ----
__global__ __launch_bounds__(256) void proj_kq_pr(
    const float* __restrict__ pos, const float* __restrict__ rot,
    const float* __restrict__ w_pos, const float* __restrict__ b_pos,
    const float* __restrict__ w_rot)
{
    __shared__ float sp[16][6], sr[16][4];
    const int i0 = blockIdx.x * 16, tid = threadIdx.x;
    if (tid < 16) {
        int i = i0 + tid;
        float p0 = pos[i*3], p1 = pos[i*3+1], p2 = pos[i*3+2];
        sp[tid][0]=cosf(PI2*p0); sp[tid][1]=cosf(PI2*p1); sp[tid][2]=cosf(PI2*p2);
        sp[tid][3]=sinf(PI2*p0); sp[tid][4]=sinf(PI2*p1); sp[tid][5]=sinf(PI2*p2);
        sr[tid][0]=rot[i*4]; sr[tid][1]=rot[i*4+1]; sr[tid][2]=rot[i*4+2]; sr[tid][3]=rot[i*4+3];
    }
    __syncthreads();

    for (int o = tid; o < 512; o += 256) {
        float acc[16], b = b_pos[o];
        #pragma unroll
        for (int r = 0; r < 16; r++) acc[r] = b;
        const float* w = w_pos + o*6;
        for (int kk = 0; kk < 6; kk++) {
            float wv = __ldg(w+kk);
            #pragma unroll
            for (int r = 0; r < 16; r++) acc[r] += wv * sp[r][kk];
        }
        int hh = (o>>6)+8, cx = o&63;
        float* dst = ((cx<32)?g_k:g_q) + (hh*NC + (cx&31))*SEQ + i0;
        #pragma unroll
        for (int r4 = 0; r4 < 4; r4++)
            ((float4*)dst)[r4] = make_float4(acc[4*r4],acc[4*r4+1],acc[4*r4+2],acc[4*r4+3]);
    }
    for (int o = tid; o < 512; o += 256) {
        float acc[16];
        #pragma unroll
        for (int r = 0; r < 16; r++) acc[r] = 0.f;
        const float* w = w_rot + o*4;
        for (int kk = 0; kk < 4; kk++) {
            float wv = __ldg(w+kk);
            #pragma unroll
            for (int r = 0; r < 16; r++) acc[r] += wv * sr[r][kk];
        }
        int hh = (o>>6)+16, cx = o&63;
        float* dst = ((cx<32)?g_k:g_q) + (hh*NC + (cx&31))*SEQ + i0;
        #pragma unroll
        for (int r4 = 0; r4 < 4; r4++)
            ((float4*)dst)[r4] = make_float4(acc[4*r4],acc[4*r4+1],acc[4*r4+2],acc[4*r4+3]);
    }
}

// pack nodes into bf16 hi/lo m16k16 A-frags
__global__ __launch_bounds__(256) void pack_nodes_kernel(const float* __restrict__ nodes)
{
    int id = blockIdx.x*256 + threadIdx.x;
    int lane = id&31, kt = (id>>5)&7, jt = id>>8;
    int g = lane>>2, tig = lane&3;
    int r0 = jt*16+g, c0 = kt*16+2*tig;
    float2 v00 = *(const float2*)&nodes[r0*128 + c0];
    float2 v10 = *(const float2*)&nodes[(r0+8)*128 + c0];
    float2 v01 = *(const float2*)&nodes[r0*128 + c0+8];
    float2 v11 = *(const float2*)&nodes[(r0+8)*128 + c0+8];
    float h00=bfr(v00.x), h01=bfr(v00.y), h10=bfr(v10.x), h11=bfr(v10.y);
    float h20=bfr(v01.x), h21=bfr(v01.y), h30=bfr(v11.x), h31=bfr(v11.y);
    size_t base = (size_t)(jt*8+kt)*4*32 + lane;
    g_na[base]    = ((u64)bf2(h10,h11)<<32) | bf2(h00,h01);
    g_na[base+32] = ((u64)bf2(h30,h31)<<32) | bf2(h20,h21);
    g_na[base+64] = ((u64)bf2(v10.x-h10,v10.y-h11)<<32) | bf2(v00.x-h00,v00.y-h01);
    g_na[base+96] = ((u64)bf2(v11.x-h30,v11.y-h31)<<32) | bf2(v01.x-h20,v01.y-h21);
}

// pack a row-major [O x 128] weight into bf16 hi/lo m16n8k16 B-frags.
// which=0 -> g_wb (w_values), which=1 -> g_wkq (w_nodes_kq).
// (NOTE: destination selected in DEVICE code — host must never take the
// address of a __device__ symbol; that was the R12 bug.)
__global__ __launch_bounds__(256) void pack_w_kernel(const float* __restrict__ w, int which)
{
    u64* __restrict__ dst = which ? g_wkq : g_wb;
    int id = blockIdx.x*256 + threadIdx.x;
    int lane = id&31, kt = (id>>5)&7, nt = id>>8;
    int g = lane>>2, tig = lane&3;
    int o = nt*8+g, c0 = kt*16+2*tig;
    float2 wa = *(const float2*)&w[o*128 + c0];
    float2 wb = *(const float2*)&w[o*128 + c0+8];
    float ha0=bfr(wa.x), ha1=bfr(wa.y), hb0=bfr(wb.x), hb1=bfr(wb.y);
    size_t base = (size_t)(nt*8+kt)*2*32 + lane;
    dst[base]    = ((u64)bf2(hb0,hb1)<<32) | bf2(ha0,ha1);
    dst[base+32] = ((u64)bf2(wb.x-hb0,wb.y-hb1)<<32) | bf2(wa.x-ha0,wa.y-ha1);
}

// nodes k/q projection (heads 0..7) as 3-pass split-bf16 mma GEMM
#define KQ_SMEM (16384 + 65536)
__global__ __launch_bounds__(256) void proj_kq_mma(const float* __restrict__ bias)
{
    extern __shared__ __align__(16) unsigned char sm[];
    u64* sA = (u64*)sm;                  // 2048 u64
    u64* sB = (u64*)(sm + 16384);        // 8192 u64
    float* sO = (float*)(sm + 16384);    // [32 j][133] (overlaps sB after mainloop)

    const int tid = threadIdx.x, w = tid>>5, lane = tid&31;
    const int g = lane>>2, tig = lane&3;
    const int jb = blockIdx.x, oy = blockIdx.y;
    const int jw = w>>2, dw = w&3;

    const float4* srcA = (const float4*)(g_na + (size_t)(jb*2)*8*4*32);
    for (int f = tid; f < 1024; f += 256) cpa16((float4*)sA + f, srcA + f);
    const float4* srcB = (const float4*)(g_wkq + (size_t)oy*16*8*2*32);
    for (int f = tid; f < 4096; f += 256) cpa16((float4*)sB + f, srcB + f);
    CP_COMMIT();
    CP_WAIT0();
    __syncthreads();

    float acc[4][4];
    #pragma unroll
    for (int nt = 0; nt < 4; nt++) { acc[nt][0]=0.f; acc[nt][1]=0.f; acc[nt][2]=0.f; acc[nt][3]=0.f; }

    const u64* A = sA + (size_t)jw*(8*4*32);
    const u64* B = sB + (size_t)dw*4*(8*2*32);
    #pragma unroll
    for (int kt = 0; kt < 8; kt++) {
        u64 h01 = A[(kt*4+0)*32+lane], h23 = A[(kt*4+1)*32+lane];
        u64 l01 = A[(kt*4+2)*32+lane], l23 = A[(kt*4+3)*32+lane];
        u32 ah[4] = {(u32)h01,(u32)(h01>>32),(u32)h23,(u32)(h23>>32)};
        u32 al[4] = {(u32)l01,(u32)(l01>>32),(u32)l23,(u32)(l23>>32)};
        #pragma unroll
        for (int nt = 0; nt < 4; nt++) {
            u64 bh = B[((nt*8+kt)*2+0)*32+lane];
            u64 bl = B[((nt*8+kt)*2+1)*32+lane];
            mma16b(acc[nt], ah, (u32)bh, (u32)(bh>>32));
            mma16b(acc[nt], al, (u32)bh, (u32)(bh>>32));
            mma16b(acc[nt], ah, (u32)bl, (u32)(bl>>32));
        }
    }
    __syncthreads();   // all sB reads done before sO overwrite

    #pragma unroll
    for (int nt = 0; nt < 4; nt++) {
        int d = dw*32 + nt*8 + 2*tig;
        int o = oy*128 + d;
        float b0 = __ldg(&bias[o]), b1 = __ldg(&bias[o+1]);
        int j0 = jw*16 + g;
        sO[j0*133 + d]       = acc[nt][0] + b0;
        sO[j0*133 + d + 1]   = acc[nt][1] + b1;
        sO[(j0+8)*133 + d]   = acc[nt][2] + b0;
        sO[(j0+8)*133 + d+1] = acc[nt][3] + b1;
    }
    __syncthreads();

    // transpose scatter: coalesced 128B per output column
    for (int f = tid; f < 4096; f += 256) {
        int ol = f >> 5, j = f & 31;
        int o = oy*128 + ol;
        int hh = o >> 6, cx = o & 63;
        float* dst = ((cx < 32) ? g_k : g_q) + (size_t)(hh*NC + (cx & 31))*SEQ + jb*32 + j;
        *dst = sO[j*133 + ol];
    }
}

// values projection as 3-pass split-bf16 mma GEMM, writing g_vp frags directly
#define PV_SMEM (16384 + 65536 + 8448)
__global__ __launch_bounds__(256) void proj_val_mma(const float* __restrict__ b_values)
{
    extern __shared__ __align__(16) unsigned char sm[];
    u64* sA = (u64*)sm;
    u64* sB = (u64*)(sm + 16384);
    __half* sO = (__half*)(sm + 81920);   // [32 j][132]

    const int tid = threadIdx.x, w = tid>>5, lane = tid&31;
    const int g = lane>>2, tig = lane&3;
    const int jb = blockIdx.x, h = blockIdx.y;
    const int jw = w>>2, dw = w&3;

    const float4* srcA = (const float4*)(g_na + (size_t)(jb*2)*8*4*32);
    for (int f = tid; f < 1024; f += 256) cpa16((float4*)sA + f, srcA + f);
    const float4* srcB = (const float4*)(g_wb + (size_t)h*16*8*2*32);
    for (int f = tid; f < 4096; f += 256) cpa16((float4*)sB + f, srcB + f);
    CP_COMMIT();
    CP_WAIT0();
    __syncthreads();

    float acc[4][4];
    #pragma unroll
    for (int nt = 0; nt < 4; nt++) { acc[nt][0]=0.f; acc[nt][1]=0.f; acc[nt][2]=0.f; acc[nt][3]=0.f; }

    const u64* A = sA + (size_t)jw*(8*4*32);
    const u64* B = sB + (size_t)dw*4*(8*2*32);
    #pragma unroll
    for (int kt = 0; kt < 8; kt++) {
        u64 h01 = A[(kt*4+0)*32+lane], h23 = A[(kt*4+1)*32+lane];
        u64 l01 = A[(kt*4+2)*32+lane], l23 = A[(kt*4+3)*32+lane];
        u32 ah[4] = {(u32)h01,(u32)(h01>>32),(u32)h23,(u32)(h23>>32)};
        u32 al[4] = {(u32)l01,(u32)(l01>>32),(u32)l23,(u32)(l23>>32)};
        #pragma unroll
        for (int nt = 0; nt < 4; nt++) {
            u64 bh = B[((nt*8+kt)*2+0)*32+lane];
            u64 bl = B[((nt*8+kt)*2+1)*32+lane];
            mma16b(acc[nt], ah, (u32)bh, (u32)(bh>>32));
            mma16b(acc[nt], al, (u32)bh, (u32)(bh>>32));
            mma16b(acc[nt], ah, (u32)bl, (u32)(bl>>32));
        }
    }

    #pragma unroll
    for (int nt = 0; nt < 4; nt++) {
        int d = dw*32 + nt*8 + 2*tig;
        float b0 = __ldg(&b_values[h*128 + d]);
        float b1 = __ldg(&b_values[h*128 + d + 1]);
        int j0 = jw*16 + g;
        *(__half2*)&sO[j0*132 + d]     = __floats2half2_rn(acc[nt][0]+b0, acc[nt][1]+b1);
        *(__half2*)&sO[(j0+8)*132 + d] = __floats2half2_rn(acc[nt][2]+b0, acc[nt][3]+b1);
    }
    __syncthreads();

    u64* dst = g_vp + ((size_t)h*64 + jb)*1024;
    #pragma unroll
    for (int q = 0; q < 4; q++) {
        int f = tid*4 + q;
        int lv = f&31, ntv = (f>>5)&15, ktv = f>>9;
        int gv = lv>>2, tv = lv&3;
        int d = ntv*8 + gv, j = ktv*16;
        __half2 x = __halves2half2(sO[(j+2*tv)*132+d],   sO[(j+2*tv+1)*132+d]);
        __half2 y = __halves2half2(sO[(j+2*tv+8)*132+d], sO[(j+2*tv+9)*132+d]);
        dst[f] = ((u64)(*(u32*)&y)<<32) | (*(u32*)&x);
    }
}

__global__ __launch_bounds__(256) void pack_qb_kernel()
{
    int id = blockIdx.x*256 + threadIdx.x;
    int lane = id&31, nt = (id>>5)&3, kt = (id>>7)&1, ch = (id>>8)&63, h = id>>14;
    int g = lane>>2, tig = lane&3;
    int c0 = kt*16 + 2*tig, j = ch*32 + nt*8 + g;
    float q00 = g_q[(h*NC+c0  )*SEQ + j];
    float q01 = g_q[(h*NC+c0+1)*SEQ + j];
    float q08 = g_q[(h*NC+c0+8)*SEQ + j];
    float q09 = g_q[(h*NC+c0+9)*SEQ + j];
    float h00 = bfr(q00), h01 = bfr(q01), h08 = bfr(q08), h09 = bfr(q09);
    u32 hx = bf2(h00, h01), hy = bf2(h08, h09);
    u32 lx = bf2(q00-h00, q01-h01), ly = bf2(q08-h08, q09-h09);
    size_t base = ((size_t)h*64 + ch)*512 + kt*128 + nt*32 + lane;
    g_qp[base]       = ((u64)hy<<32) | hx;
    g_qp[base + 256] = ((u64)ly<<32) | lx;
}

// attention: 128 rows/block, 8 warps; QK bf16 3-pass, PV fp16 k16 single-pass
#define SMEM_DYN (2*4096 + 2*8192 + 8*1152)
__global__ __launch_bounds__(256) void attn_kernel()
{
    extern __shared__ __align__(16) unsigned char dsm[];
    u64* qbuf = (u64*)dsm;                 // 2 x 512 u64
    u64* vbuf = (u64*)(dsm + 8192);        // 2 x 1024 u64

    const int tid = threadIdx.x, w = tid>>5, lane = tid&31;
    const int g = lane>>2, tig = lane&3;
    const int h = blockIdx.y, i0 = blockIdx.x*128, iw = i0 + 16*w;
    u32* pP = (u32*)(dsm + 24576) + w*288; // [16][18] u32 per warp

    u32 ah[2][4], al[2][4];
    #pragma unroll
    for (int kt = 0; kt < 2; kt++) {
        int c0 = kt*16 + 2*tig;
        float kv[4][2];
        #pragma unroll
        for (int e = 0; e < 4; e++) {
            int c = c0 + (e>>1)*8;
            int i = iw + g + (e&1)*8;
            kv[e][0] = g_k[(h*NC + c)*SEQ + i];
            kv[e][1] = g_k[(h*NC + c+1)*SEQ + i];
        }
        #pragma unroll
        for (int e = 0; e < 4; e++) {
            float h0 = bfr(kv[e][0]);
            float h1 = bfr(kv[e][1]);
            ah[kt][e] = bf2(h0, h1);
            al[kt][e] = bf2(kv[e][0]-h0, kv[e][1]-h1);
        }
    }

    float o[16][4];
    #pragma unroll
    for (int nt = 0; nt < 16; nt++) { o[nt][0]=0.f; o[nt][1]=0.f; o[nt][2]=0.f; o[nt][3]=0.f; }
    float m0 = -1e30f, m1 = -1e30f, s0 = 0.f, s1 = 0.f;

    const u64* gqp = g_qp + (size_t)h*64*512;
    const u64* gvp = g_vp + (size_t)h*64*1024;
    const bool sqh = (h >= 16);

    {
        cpa16((float4*)qbuf + tid, (const float4*)gqp + tid);
        #pragma unroll
        for (int r = 0; r < 2; r++) cpa16((float4*)vbuf + tid + 256*r, (const float4*)gvp + tid + 256*r);
        CP_COMMIT();
    }

    for (int ch = 0; ch < 64; ch++) {
        int cur = ch & 1;
        if (ch < 63) {
            int nb = (ch+1) & 1;
            const float4* sq = (const float4*)(gqp + (size_t)(ch+1)*512);
            const float4* sv = (const float4*)(gvp + (size_t)(ch+1)*1024);
            cpa16((float4*)(qbuf + nb*512) + tid, sq + tid);
            #pragma unroll
            for (int r = 0; r < 2; r++) cpa16((float4*)(vbuf + nb*1024) + tid + 256*r, sv + tid + 256*r);
        }
        CP_COMMIT();
        CP_WAIT1();
        __syncthreads();

        const u64* sqp = qbuf + cur*512;
        const u64* svp = vbuf + cur*1024;

        float C[4][4];
        #pragma unroll
        for (int nt = 0; nt < 4; nt++) { C[nt][0]=0.f; C[nt][1]=0.f; C[nt][2]=0.f; C[nt][3]=0.f; }
        #pragma unroll
        for (int kt = 0; kt < 2; kt++) {
            #pragma unroll
            for (int nt = 0; nt < 4; nt++) {
                u64 bh = sqp[kt*128 + nt*32 + lane];
                u64 bl = sqp[256 + kt*128 + nt*32 + lane];
                u32 bh0 = (u32)bh, bh1 = (u32)(bh>>32);
                mma16b(C[nt], ah[kt], bh0, bh1);
                mma16b(C[nt], al[kt], bh0, bh1);
                mma16b(C[nt], ah[kt], (u32)bl, (u32)(bl>>32));
            }
        }
        if (sqh) {
            #pragma unroll
            for (int nt = 0; nt < 4; nt++) {
                C[nt][0]*=C[nt][0]; C[nt][1]*=C[nt][1]; C[nt][2]*=C[nt][2]; C[nt][3]*=C[nt][3];
            }
        }

        float cm0 = -1e30f, cm1 = -1e30f;
        #pragma unroll
        for (int nt = 0; nt < 4; nt++) {
            cm0 = fmaxf(cm0, fmaxf(C[nt][0], C[nt][1]));
            cm1 = fmaxf(cm1, fmaxf(C[nt][2], C[nt][3]));
        }
        cm0 = fmaxf(cm0, __shfl_xor_sync(0xffffffffu, cm0, 1));
        cm0 = fmaxf(cm0, __shfl_xor_sync(0xffffffffu, cm0, 2));
        cm1 = fmaxf(cm1, __shfl_xor_sync(0xffffffffu, cm1, 1));
        cm1 = fmaxf(cm1, __shfl_xor_sync(0xffffffffu, cm1, 2));
        float nm0 = fmaxf(m0, cm0), nm1 = fmaxf(m1, cm1);
        bool noup = (nm0 == m0) & (nm1 == m1);
        float ca0 = __expf(m0 - nm0), ca1 = __expf(m1 - nm1);
        m0 = nm0; m1 = nm1;

        float p[4][4];
        float cs0 = 0.f, cs1 = 0.f;
        #pragma unroll
        for (int nt = 0; nt < 4; nt++) {
            p[nt][0] = __expf(C[nt][0] - nm0);
            p[nt][1] = __expf(C[nt][1] - nm0);
            p[nt][2] = __expf(C[nt][2] - nm1);
            p[nt][3] = __expf(C[nt][3] - nm1);
            cs0 += p[nt][0] + p[nt][1];
            cs1 += p[nt][2] + p[nt][3];
        }
        cs0 += __shfl_xor_sync(0xffffffffu, cs0, 1);
        cs0 += __shfl_xor_sync(0xffffffffu, cs0, 2);
        cs1 += __shfl_xor_sync(0xffffffffu, cs1, 1);
        cs1 += __shfl_xor_sync(0xffffffffu, cs1, 2);
        s0 = s0*ca0 + cs0;
        s1 = s1*ca1 + cs1;
        if (!__all_sync(0xffffffffu, noup)) {
            #pragma unroll
            for (int nt = 0; nt < 16; nt++) {
                o[nt][0] *= ca0; o[nt][1] *= ca0;
                o[nt][2] *= ca1; o[nt][3] *= ca1;
            }
        }

        #pragma unroll
        for (int nt = 0; nt < 4; nt++) {
            pP[g*18     + nt*4 + tig] = hf2(p[nt][0], p[nt][1]);
            pP[(g+8)*18 + nt*4 + tig] = hf2(p[nt][2], p[nt][3]);
        }
        __syncwarp();
        u32 pa[2][4];
        #pragma unroll
        for (int kt = 0; kt < 2; kt++) {
            pa[kt][0] = pP[g*18     + kt*8 + tig];
            pa[kt][1] = pP[(g+8)*18 + kt*8 + tig];
            pa[kt][2] = pP[g*18     + kt*8 + tig + 4];
            pa[kt][3] = pP[(g+8)*18 + kt*8 + tig + 4];
        }

        #pragma unroll
        for (int kt = 0; kt < 2; kt++) {
            #pragma unroll
            for (int nt = 0; nt < 16; nt++) {
                u64 bv = svp[kt*512 + nt*32 + lane];
                mma16h(o[nt], pa[kt], (u32)bv, (u32)(bv>>32));
            }
        }
        __syncthreads();
    }

    float inv0 = 1.f/s0, inv1 = 1.f/s1;
    __half* gp = g_part + ((size_t)h*SEQ + iw)*ND;
    #pragma unroll
    for (int nt = 0; nt < 16; nt++) {
        *(__half2*)&gp[(size_t)g*ND + nt*8 + 2*tig]     = __floats2half2_rn(o[nt][0]*inv0, o[nt][1]*inv0);
        *(__half2*)&gp[(size_t)(g+8)*ND + nt*8 + 2*tig] = __floats2half2_rn(o[nt][2]*inv1, o[nt][3]*inv1);
    }
}

__global__ __launch_bounds__(256) void reduce_kernel(float* __restrict__ out)
{
    int idx = blockIdx.x*256 + threadIdx.x;     // over SEQ*ND/2
    const u32* gp = (const u32*)g_part;
    float2 s = make_float2(0.f, 0.f);
    #pragma unroll
    for (int hh = 0; hh < NH; hh++) {
        u32 v = gp[(size_t)hh*(SEQ*ND/2) + idx];
        float2 f = __half22float2(*(__half2*)&v);
        s.x += f.x; s.y += f.y;
    }
    ((float2*)out)[idx] = s;
}

extern "C" void kernel_launch(void* const* d_in, const int* in_sizes, int n_in,
                              void* d_out, int out_size)
{
    const float* nodes = (const float*)d_in[0];
    const float* pos   = (const float*)d_in[1];
    const float* rot   = (const float*)d_in[2];

    cudaFuncSetAttribute(proj_kq_mma,  cudaFuncAttributeMaxDynamicSharedMemorySize, KQ_SMEM);
    cudaFuncSetAttribute(proj_val_mma, cudaFuncAttributeMaxDynamicSharedMemorySize, PV_SMEM);
    cudaFuncSetAttribute(attn_kernel,  cudaFuncAttributeMaxDynamicSharedMemorySize, SMEM_DYN);

    pack_nodes_kernel<<<128, 256>>>(nodes);
    pack_w_kernel<<<384, 256>>>((const float*)d_in[8], 0);   // -> g_wb
    pack_w_kernel<<<64, 256>>>((const float*)d_in[3], 1);    // -> g_wkq

    dim3 gkq(64, 4);
    proj_kq_mma<<<gkq, 256, KQ_SMEM>>>((const float*)d_in[4]);
    proj_kq_pr<<<SEQ/16, 256>>>(pos, rot,
        (const float*)d_in[5], (const float*)d_in[6], (const float*)d_in[7]);

    pack_qb_kernel<<<1536, 256>>>();
    dim3 gpv(64, NH);
    proj_val_mma<<<gpv, 256, PV_SMEM>>>((const float*)d_in[9]);
    dim3 ga(SEQ/128, NH);
    attn_kernel<<<ga, 256, SMEM_DYN>>>();
    reduce_kernel<<<(SEQ*ND/2)/256, 256>>>((float*)d_out);
}

// round 16
// speedup vs baseline: 5.7418x; 1.0326x over previous
#include <cuda_runtime.h>
#include <cuda_bf16.h>
#include <cuda_fp16.h>
#include <math.h>

#define SEQ 2048
#define ND  128
#define NH  24
#define NC  32
#define PI2 6.283185307179586f

typedef unsigned long long u64;
typedef unsigned int u32;

__device__ float  g_k[NH*NC*SEQ];     // [h][c][i]
__device__ float  g_q[NH*NC*SEQ];     // [h][c][j]
__device__ u64    g_qp[NH*64*512];    // bf16 q B-frags (hi 256 / lo 256 per chunk)
__device__ u64    g_vp[NH*64*1024];   // fp16 v B-frags (k16)
__device__ u64    g_na[128*8*4*32];   // nodes bf16 hi/lo A-frags
__device__ u64    g_wb[384*8*2*32];   // w_values bf16 hi/lo B-frags
__device__ u64    g_wkq[64*8*2*32];   // w_nodes_kq bf16 hi/lo B-frags
__device__ __half g_part[NH*SEQ*ND];  // fp16 per-head partials

__device__ __forceinline__ u32 bf2(float lo, float hi){
    u32 r; asm("cvt.rn.bf16x2.f32 %0,%1,%2;" : "=r"(r) : "f"(hi), "f"(lo)); return r;
}
__device__ __forceinline__ u32 hf2(float lo, float hi){
    __half2 h = __floats2half2_rn(lo, hi);
    return *(u32*)&h;
}
__device__ __forceinline__ float bfr(float x){ return __bfloat162float(__float2bfloat16_rn(x)); }

__device__ __forceinline__ void mma16b(float* c, const u32* a, u32 b0, u32 b1){
    asm volatile("mma.sync.aligned.m16n8k16.row.col.f32.bf16.bf16.f32 "
        "{%0,%1,%2,%3},{%4,%5,%6,%7},{%8,%9},{%0,%1,%2,%3};"
        : "+f"(c[0]),"+f"(c[1]),"+f"(c[2]),"+f"(c[3])
        : "r"(a[0]),"r"(a[1]),"r"(a[2]),"r"(a[3]),"r"(b0),"r"(b1));
}
__device__ __forceinline__ void mma16h(float* c, const u32* a, u32 b0, u32 b1){
    asm volatile("mma.sync.aligned.m16n8k16.row.col.f32.f16.f16.f32 "
        "{%0,%1,%2,%3},{%4,%5,%6,%7},{%8,%9},{%0,%1,%2,%3};"
        : "+f"(c[0]),"+f"(c[1]),"+f"(c[2]),"+f"(c[3])
        : "r"(a[0]),"r"(a[1]),"r"(a[2]),"r"(a[3]),"r"(b0),"r"(b1));
}

__device__ __forceinline__ void cpa16(void* smem, const void* gmem){
    u32 s = (u32)__cvta_generic_to_shared(smem);
    asm volatile("cp.async.cg.shared.global [%0], [%1], 16;" :: "r"(s), "l"(gmem));
}
#define CP_COMMIT() asm volatile("cp.async.commit_group;")
#define CP_WAIT1()  asm volatile("cp.async.wait_group 1;")
#define CP_WAIT0()  asm volatile("cp.async.wait_group 0;")

// ---- pos/rot k-q projections (heads 8..23) — scalar, tiny ----
__global__ __launch_bounds__(256) void proj_kq_pr(
    const float* __restrict__ pos, const float* __restrict__ rot,
    const float* __restrict__ w_pos, const float* __restrict__ b_pos,
    const float* __restrict__ w_rot)
{
    __shared__ float sp[16][6], sr[16][4];
    const int i0 = blockIdx.x * 16, tid = threadIdx.x;
    if (tid < 16) {
        int i = i0 + tid;
        float p0 = pos[i*3], p1 = pos[i*3+1], p2 = pos[i*3+2];
        sp[tid][0]=cosf(PI2*p0); sp[tid][1]=cosf(PI2*p1); sp[tid][2]=cosf(PI2*p2);
        sp[tid][3]=sinf(PI2*p0); sp[tid][4]=sinf(PI2*p1); sp[tid][5]=sinf(PI2*p2);
        sr[tid][0]=rot[i*4]; sr[tid][1]=rot[i*4+1]; sr[tid][2]=rot[i*4+2]; sr[tid][3]=rot[i*4+3];
    }
    __syncthreads();

    for (int o = tid; o < 512; o += 256) {
        float acc[16], b = b_pos[o];
        #pragma unroll
        for (int r = 0; r < 16; r++) acc[r] = b;
        const float* w = w_pos + o*6;
        for (int kk = 0; kk < 6; kk++) {
            float wv = __ldg(w+kk);
            #pragma unroll
            for (int r = 0; r < 16; r++) acc[r] += wv * sp[r][kk];
        }
        int hh = (o>>6)+8, cx = o&63;
        float* dst = ((cx<32)?g_k:g_q) + (hh*NC + (cx&31))*SEQ + i0;
        #pragma unroll
        for (int r4 = 0; r4 < 4; r4++)
            ((float4*)dst)[r4] = make_float4(acc[4*r4],acc[4*r4+1],acc[4*r4+2],acc[4*r4+3]);
    }
    for (int o = tid; o < 512; o += 256) {
        float acc[16];
        #pragma unroll
        for (int r = 0; r < 16; r++) acc[r] = 0.f;
        const float* w = w_rot + o*4;
        for (int kk = 0; kk < 4; kk++) {
            float wv = __ldg(w+kk);
            #pragma unroll
            for (int r = 0; r < 16; r++) acc[r] += wv * sr[r][kk];
        }
        int hh = (o>>6)+16, cx = o&63;
        float* dst = ((cx<32)?g_k:g_q) + (hh*NC + (cx&31))*SEQ + i0;
        #pragma unroll
        for (int r4 = 0; r4 < 4; r4++)
            ((float4*)dst)[r4] = make_float4(acc[4*r4],acc[4*r4+1],acc[4*r4+2],acc[4*r4+3]);
    }
}

// pack nodes into bf16 hi/lo m16k16 A-frags
__global__ __launch_bounds__(256) void pack_nodes_kernel(const float* __restrict__ nodes)
{
    int id = blockIdx.x*256 + threadIdx.x;
    int lane = id&31, kt = (id>>5)&7, jt = id>>8;
    int g = lane>>2, tig = lane&3;
    int r0 = jt*16+g, c0 = kt*16+2*tig;
    float2 v00 = *(const float2*)&nodes[r0*128 + c0];
    float2 v10 = *(const float2*)&nodes[(r0+8)*128 + c0];
    float2 v01 = *(const float2*)&nodes[r0*128 + c0+8];
    float2 v11 = *(const float2*)&nodes[(r0+8)*128 + c0+8];
    float h00=bfr(v00.x), h01=bfr(v00.y), h10=bfr(v10.x), h11=bfr(v10.y);
    float h20=bfr(v01.x), h21=bfr(v01.y), h30=bfr(v11.x), h31=bfr(v11.y);
    size_t base = (size_t)(jt*8+kt)*4*32 + lane;
    g_na[base]    = ((u64)bf2(h10,h11)<<32) | bf2(h00,h01);
    g_na[base+32] = ((u64)bf2(h30,h31)<<32) | bf2(h20,h21);
    g_na[base+64] = ((u64)bf2(v10.x-h10,v10.y-h11)<<32) | bf2(v00.x-h00,v00.y-h01);
    g_na[base+96] = ((u64)bf2(v11.x-h30,v11.y-h31)<<32) | bf2(v01.x-h20,v01.y-h21);
}

// pack a row-major [O x 128] weight into bf16 hi/lo m16n8k16 B-frags.
// which=0 -> g_wb (w_values), which=1 -> g_wkq (w_nodes_kq).
// Destination chosen in DEVICE code (host must never take &__device__ symbol).
__global__ __launch_bounds__(256) void pack_w_kernel(const float* __restrict__ w, int which)
{
    u64* __restrict__ dst = which ? g_wkq : g_wb;
    int id = blockIdx.x*256 + threadIdx.x;
    int lane = id&31, kt = (id>>5)&7, nt = id>>8;
    int g = lane>>2, tig = lane&3;
    int o = nt*8+g, c0 = kt*16+2*tig;
    float2 wa = *(const float2*)&w[o*128 + c0];
    float2 wb = *(const float2*)&w[o*128 + c0+8];
    float ha0=bfr(wa.x), ha1=bfr(wa.y), hb0=bfr(wb.x), hb1=bfr(wb.y);
    size_t base = (size_t)(nt*8+kt)*2*32 + lane;
    dst[base]    = ((u64)bf2(hb0,hb1)<<32) | bf2(ha0,ha1);
    dst[base+32] = ((u64)bf2(wb.x-hb0,wb.y-hb1)<<32) | bf2(wa.x-ha0,wa.y-ha1);
}

// nodes k/q projection (heads 0..7) as 3-pass split-bf16 mma GEMM
#define KQ_SMEM (16384 + 65536)
__global__ __launch_bounds__(256) void proj_kq_mma(const float* __restrict__ bias)
{
    extern __shared__ __align__(16) unsigned char sm[];
    u64* sA = (u64*)sm;                  // 2048 u64
    u64* sB = (u64*)(sm + 16384);        // 8192 u64
    float* sO = (float*)(sm + 16384);    // [32 j][133] (overlaps sB after mainloop)

    const int tid = threadIdx.x, w = tid>>5, lane = tid&31;
    const int g = lane>>2, tig = lane&3;
    const int jb = blockIdx.x, oy = blockIdx.y;
    const int jw = w>>2, dw = w&3;

    const float4* srcA = (const float4*)(g_na + (size_t)(jb*2)*8*4*32);
    for (int f = tid; f < 1024; f += 256) cpa16((float4*)sA + f, srcA + f);
    const float4* srcB = (const float4*)(g_wkq + (size_t)oy*16*8*2*32);
    for (int f = tid; f < 4096; f += 256) cpa16((float4*)sB + f, srcB + f);
    CP_COMMIT();
    CP_WAIT0();
    __syncthreads();

    float acc[4][4];
    #pragma unroll
    for (int nt = 0; nt < 4; nt++) { acc[nt][0]=0.f; acc[nt][1]=0.f; acc[nt][2]=0.f; acc[nt][3]=0.f; }

    const u64* A = sA + (size_t)jw*(8*4*32);
    const u64* B = sB + (size_t)dw*4*(8*2*32);
    #pragma unroll
    for (int kt = 0; kt < 8; kt++) {
        u64 h01 = A[(kt*4+0)*32+lane], h23 = A[(kt*4+1)*32+lane];
        u64 l01 = A[(kt*4+2)*32+lane], l23 = A[(kt*4+3)*32+lane];
        u32 ah[4] = {(u32)h01,(u32)(h01>>32),(u32)h23,(u32)(h23>>32)};
        u32 al[4] = {(u32)l01,(u32)(l01>>32),(u32)l23,(u32)(l23>>32)};
        #pragma unroll
        for (int nt = 0; nt < 4; nt++) {
            u64 bh = B[((nt*8+kt)*2+0)*32+lane];
            u64 bl = B[((nt*8+kt)*2+1)*32+lane];
            mma16b(acc[nt], ah, (u32)bh, (u32)(bh>>32));
            mma16b(acc[nt], al, (u32)bh, (u32)(bh>>32));
            mma16b(acc[nt], ah, (u32)bl, (u32)(bl>>32));
        }
    }
    __syncthreads();   // all sB reads done before sO overwrite

    #pragma unroll
    for (int nt = 0; nt < 4; nt++) {
        int d = dw*32 + nt*8 + 2*tig;
        int o = oy*128 + d;
        float b0 = __ldg(&bias[o]), b1 = __ldg(&bias[o+1]);
        int j0 = jw*16 + g;
        sO[j0*133 + d]       = acc[nt][0] + b0;
        sO[j0*133 + d + 1]   = acc[nt][1] + b1;
        sO[(j0+8)*133 + d]   = acc[nt][2] + b0;
        sO[(j0+8)*133 + d+1] = acc[nt][3] + b1;
    }
    __syncthreads();

    // transpose scatter: coalesced 128B per output column
    for (int f = tid; f < 4096; f += 256) {
        int ol = f >> 5, j = f & 31;
        int o = oy*128 + ol;
        int hh = o >> 6, cx = o & 63;
        float* dst = ((cx < 32) ? g_k : g_q) + (size_t)(hh*NC + (cx & 31))*SEQ + jb*32 + j;
        *dst = sO[j*133 + ol];
    }
}

// values projection as 3-pass split-bf16 mma GEMM, writing g_vp frags directly
#define PV_SMEM (16384 + 65536 + 8448)
__global__ __launch_bounds__(256) void proj_val_mma(const float* __restrict__ b_values)
{
    extern __shared__ __align__(16) unsigned char sm[];
    u64* sA = (u64*)sm;
    u64* sB = (u64*)(sm + 16384);
    __half* sO = (__half*)(sm + 81920);   // [32 j][132]

    const int tid = threadIdx.x, w = tid>>5, lane = tid&31;
    const int g = lane>>2, tig = lane&3;
    const int jb = blockIdx.x, h = blockIdx.y;
    const int jw = w>>2, dw = w&3;

    const float4* srcA = (const float4*)(g_na + (size_t)(jb*2)*8*4*32);
    for (int f = tid; f < 1024; f += 256) cpa16((float4*)sA + f, srcA + f);
    const float4* srcB = (const float4*)(g_wb + (size_t)h*16*8*2*32);
    for (int f = tid; f < 4096; f += 256) cpa16((float4*)sB + f, srcB + f);
    CP_COMMIT();
    CP_WAIT0();
    __syncthreads();

    float acc[4][4];
    #pragma unroll
    for (int nt = 0; nt < 4; nt++) { acc[nt][0]=0.f; acc[nt][1]=0.f; acc[nt][2]=0.f; acc[nt][3]=0.f; }

    const u64* A = sA + (size_t)jw*(8*4*32);
    const u64* B = sB + (size_t)dw*4*(8*2*32);
    #pragma unroll
    for (int kt = 0; kt < 8; kt++) {
        u64 h01 = A[(kt*4+0)*32+lane], h23 = A[(kt*4+1)*32+lane];
        u64 l01 = A[(kt*4+2)*32+lane], l23 = A[(kt*4+3)*32+lane];
        u32 ah[4] = {(u32)h01,(u32)(h01>>32),(u32)h23,(u32)(h23>>32)};
        u32 al[4] = {(u32)l01,(u32)(l01>>32),(u32)l23,(u32)(l23>>32)};
        #pragma unroll
        for (int nt = 0; nt < 4; nt++) {
            u64 bh = B[((nt*8+kt)*2+0)*32+lane];
            u64 bl = B[((nt*8+kt)*2+1)*32+lane];
            mma16b(acc[nt], ah, (u32)bh, (u32)(bh>>32));
            mma16b(acc[nt], al, (u32)bh, (u32)(bh>>32));
            mma16b(acc[nt], ah, (u32)bl, (u32)(bl>>32));
        }
    }

    #pragma unroll
    for (int nt = 0; nt < 4; nt++) {
        int d = dw*32 + nt*8 + 2*tig;
        float b0 = __ldg(&b_values[h*128 + d]);
        float b1 = __ldg(&b_values[h*128 + d + 1]);
        int j0 = jw*16 + g;
        *(__half2*)&sO[j0*132 + d]     = __floats2half2_rn(acc[nt][0]+b0, acc[nt][1]+b1);
        *(__half2*)&sO[(j0+8)*132 + d] = __floats2half2_rn(acc[nt][2]+b0, acc[nt][3]+b1);
    }
    __syncthreads();

    u64* dst = g_vp + ((size_t)h*64 + jb)*1024;
    #pragma unroll
    for (int q = 0; q < 4; q++) {
        int f = tid*4 + q;
        int lv = f&31, ntv = (f>>5)&15, ktv = f>>9;
        int gv = lv>>2, tv = lv&3;
        int d = ntv*8 + gv, j = ktv*16;
        __half2 x = __halves2half2(sO[(j+2*tv)*132+d],   sO[(j+2*tv+1)*132+d]);
        __half2 y = __halves2half2(sO[(j+2*tv+8)*132+d], sO[(j+2*tv+9)*132+d]);
        dst[f] = ((u64)(*(u32*)&y)<<32) | (*(u32*)&x);
    }
}

__global__ __launch_bounds__(256) void pack_qb_kernel()
{
    int id = blockIdx.x*256 + threadIdx.x;
    int lane = id&31, nt = (id>>5)&3, kt = (id>>7)&1, ch = (id>>8)&63, h = id>>14;
    int g = lane>>2, tig = lane&3;
    int c0 = kt*16 + 2*tig, j = ch*32 + nt*8 + g;
    float q00 = g_q[(h*NC+c0  )*SEQ + j];
    float q01 = g_q[(h*NC+c0+1)*SEQ + j];
    float q08 = g_q[(h*NC+c0+8)*SEQ + j];
    float q09 = g_q[(h*NC+c0+9)*SEQ + j];
    float h00 = bfr(q00), h01 = bfr(q01), h08 = bfr(q08), h09 = bfr(q09);
    u32 hx = bf2(h00, h01), hy = bf2(h08, h09);
    u32 lx = bf2(q00-h00, q01-h01), ly = bf2(q08-h08, q09-h09);
    size_t base = ((size_t)h*64 + ch)*512 + kt*128 + nt*32 + lane;
    g_qp[base]       = ((u64)hy<<32) | hx;
    g_qp[base + 256] = ((u64)ly<<32) | lx;
}

// attention: 128 rows/block, 8 warps; QK bf16 3-pass, PV fp16 k16 single-pass
#define SMEM_DYN (2*4096 + 2*8192 + 8*1152)
__global__ __launch_bounds__(256) void attn_kernel()
{
    extern __shared__ __align__(16) unsigned char dsm[];
    u64* qbuf = (u64*)dsm;                 // 2 x 512 u64
    u64* vbuf = (u64*)(dsm + 8192);        // 2 x 1024 u64

    const int tid = threadIdx.x, w = tid>>5, lane = tid&31;
    const int g = lane>>2, tig = lane&3;
    const int h = blockIdx.y, i0 = blockIdx.x*128, iw = i0 + 16*w;
    u32* pP = (u32*)(dsm + 24576) + w*288; // [16][18] u32 per warp

    u32 ah[2][4], al[2][4];
    #pragma unroll
    for (int kt = 0; kt < 2; kt++) {
        int c0 = kt*16 + 2*tig;
        float kv[4][2];
        #pragma unroll
        for (int e = 0; e < 4; e++) {
            int c = c0 + (e>>1)*8;
            int i = iw + g + (e&1)*8;
            kv[e][0] = g_k[(h*NC + c)*SEQ + i];
            kv[e][1] = g_k[(h*NC + c+1)*SEQ + i];
        }
        #pragma unroll
        for (int e = 0; e < 4; e++) {
            float h0 = bfr(kv[e][0]);
            float h1 = bfr(kv[e][1]);
            ah[kt][e] = bf2(h0, h1);
            al[kt][e] = bf2(kv[e][0]-h0, kv[e][1]-h1);
        }
    }

    float o[16][4];
    #pragma unroll
    for (int nt = 0; nt < 16; nt++) { o[nt][0]=0.f; o[nt][1]=0.f; o[nt][2]=0.f; o[nt][3]=0.f; }
    float m0 = -1e30f, m1 = -1e30f, s0 = 0.f, s1 = 0.f;

    const u64* gqp = g_qp + (size_t)h*64*512;
    const u64* gvp = g_vp + (size_t)h*64*1024;
    const bool sqh = (h >= 16);

    {
        cpa16((float4*)qbuf + tid, (const float4*)gqp + tid);
        #pragma unroll
        for (int r = 0; r < 2; r++) cpa16((float4*)vbuf + tid + 256*r, (const float4*)gvp + tid + 256*r);
        CP_COMMIT();
    }

    for (int ch = 0; ch < 64; ch++) {
        int cur = ch & 1;
        if (ch < 63) {
            int nb = (ch+1) & 1;
            const float4* sq = (const float4*)(gqp + (size_t)(ch+1)*512);
            const float4* sv = (const float4*)(gvp + (size_t)(ch+1)*1024);
            cpa16((float4*)(qbuf + nb*512) + tid, sq + tid);
            #pragma unroll
            for (int r = 0; r < 2; r++) cpa16((float4*)(vbuf + nb*1024) + tid + 256*r, sv + tid + 256*r);
        }
        CP_COMMIT();
        CP_WAIT1();
        __syncthreads();

        const u64* sqp = qbuf + cur*512;
        const u64* svp = vbuf + cur*1024;

        float C[4][4];
        #pragma unroll
        for (int nt = 0; nt < 4; nt++) { C[nt][0]=0.f; C[nt][1]=0.f; C[nt][2]=0.f; C[nt][3]=0.f; }
        #pragma unroll
        for (int kt = 0; kt < 2; kt++) {
            #pragma unroll
            for (int nt = 0; nt < 4; nt++) {
                u64 bh = sqp[kt*128 + nt*32 + lane];
                u64 bl = sqp[256 + kt*128 + nt*32 + lane];
                u32 bh0 = (u32)bh, bh1 = (u32)(bh>>32);
                mma16b(C[nt], ah[kt], bh0, bh1);
                mma16b(C[nt], al[kt], bh0, bh1);
                mma16b(C[nt], ah[kt], (u32)bl, (u32)(bl>>32));
            }
        }
        if (sqh) {
            #pragma unroll
            for (int nt = 0; nt < 4; nt++) {
                C[nt][0]*=C[nt][0]; C[nt][1]*=C[nt][1]; C[nt][2]*=C[nt][2]; C[nt][3]*=C[nt][3];
            }
        }

        float cm0 = -1e30f, cm1 = -1e30f;
        #pragma unroll
        for (int nt = 0; nt < 4; nt++) {
            cm0 = fmaxf(cm0, fmaxf(C[nt][0], C[nt][1]));
            cm1 = fmaxf(cm1, fmaxf(C[nt][2], C[nt][3]));
        }
        cm0 = fmaxf(cm0, __shfl_xor_sync(0xffffffffu, cm0, 1));
        cm0 = fmaxf(cm0, __shfl_xor_sync(0xffffffffu, cm0, 2));
        cm1 = fmaxf(cm1, __shfl_xor_sync(0xffffffffu, cm1, 1));
        cm1 = fmaxf(cm1, __shfl_xor_sync(0xffffffffu, cm1, 2));
        float nm0 = fmaxf(m0, cm0), nm1 = fmaxf(m1, cm1);
        bool noup = (nm0 == m0) & (nm1 == m1);
        float ca0 = __expf(m0 - nm0), ca1 = __expf(m1 - nm1);
        m0 = nm0; m1 = nm1;

        float p[4][4];
        float cs0 = 0.f, cs1 = 0.f;
        #pragma unroll
        for (int nt = 0; nt < 4; nt++) {
            p[nt][0] = __expf(C[nt][0] - nm0);
            p[nt][1] = __expf(C[nt][1] - nm0);
            p[nt][2] = __expf(C[nt][2] - nm1);
            p[nt][3] = __expf(C[nt][3] - nm1);
            cs0 += p[nt][0] + p[nt][1];
            cs1 += p[nt][2] + p[nt][3];
        }
        cs0 += __shfl_xor_sync(0xffffffffu, cs0, 1);
        cs0 += __shfl_xor_sync(0xffffffffu, cs0, 2);
        cs1 += __shfl_xor_sync(0xffffffffu, cs1, 1);
        cs1 += __shfl_xor_sync(0xffffffffu, cs1, 2);
        s0 = s0*ca0 + cs0;
        s1 = s1*ca1 + cs1;
        if (!__all_sync(0xffffffffu, noup)) {
            #pragma unroll
            for (int nt = 0; nt < 16; nt++) {
                o[nt][0] *= ca0; o[nt][1] *= ca0;
                o[nt][2] *= ca1; o[nt][3] *= ca1;
            }
        }

        #pragma unroll
        for (int nt = 0; nt < 4; nt++) {
            pP[g*18     + nt*4 + tig] = hf2(p[nt][0], p[nt][1]);
            pP[(g+8)*18 + nt*4 + tig] = hf2(p[nt][2], p[nt][3]);
        }
        __syncwarp();
        u32 pa[2][4];
        #pragma unroll
        for (int kt = 0; kt < 2; kt++) {
            pa[kt][0] = pP[g*18     + kt*8 + tig];
            pa[kt][1] = pP[(g+8)*18 + kt*8 + tig];
            pa[kt][2] = pP[g*18     + kt*8 + tig + 4];
            pa[kt][3] = pP[(g+8)*18 + kt*8 + tig + 4];
        }

        #pragma unroll
        for (int kt = 0; kt < 2; kt++) {
            #pragma unroll
            for (int nt = 0; nt < 16; nt++) {
                u64 bv = svp[kt*512 + nt*32 + lane];
                mma16h(o[nt], pa[kt], (u32)bv, (u32)(bv>>32));
            }
        }
        __syncthreads();
    }

    float inv0 = 1.f/s0, inv1 = 1.f/s1;
    __half* gp = g_part + ((size_t)h*SEQ + iw)*ND;
    #pragma unroll
    for (int nt = 0; nt < 16; nt++) {
        *(__half2*)&gp[(size_t)g*ND + nt*8 + 2*tig]     = __floats2half2_rn(o[nt][0]*inv0, o[nt][1]*inv0);
        *(__half2*)&gp[(size_t)(g+8)*ND + nt*8 + 2*tig] = __floats2half2_rn(o[nt][2]*inv1, o[nt][3]*inv1);
    }
}

__global__ __launch_bounds__(256) void reduce_kernel(float* __restrict__ out)
{
    int idx = blockIdx.x*256 + threadIdx.x;     // over SEQ*ND/2
    const u32* gp = (const u32*)g_part;
    float2 s = make_float2(0.f, 0.f);
    #pragma unroll
    for (int hh = 0; hh < NH; hh++) {
        u32 v = gp[(size_t)hh*(SEQ*ND/2) + idx];
        float2 f = __half22float2(*(__half2*)&v);
        s.x += f.x; s.y += f.y;
    }
    ((float2*)out)[idx] = s;
}

extern "C" void kernel_launch(void* const* d_in, const int* in_sizes, int n_in,
                              void* d_out, int out_size)
{
    const float* nodes = (const float*)d_in[0];
    const float* pos   = (const float*)d_in[1];
    const float* rot   = (const float*)d_in[2];

    cudaFuncSetAttribute(proj_kq_mma,  cudaFuncAttributeMaxDynamicSharedMemorySize, KQ_SMEM);
    cudaFuncSetAttribute(proj_val_mma, cudaFuncAttributeMaxDynamicSharedMemorySize, PV_SMEM);
    cudaFuncSetAttribute(attn_kernel,  cudaFuncAttributeMaxDynamicSharedMemorySize, SMEM_DYN);

    // Fork-join stream overlap of the auxiliary DAG (graph-capture-legal).
    cudaStream_t s1, s2;
    cudaStreamCreateWithFlags(&s1, cudaStreamNonBlocking);
    cudaStreamCreateWithFlags(&s2, cudaStreamNonBlocking);
    cudaEvent_t eRoot, eN, e1, e2;
    cudaEventCreateWithFlags(&eRoot, cudaEventDisableTiming);
    cudaEventCreateWithFlags(&eN,    cudaEventDisableTiming);
    cudaEventCreateWithFlags(&e1,    cudaEventDisableTiming);
    cudaEventCreateWithFlags(&e2,    cudaEventDisableTiming);

    cudaEventRecord(eRoot, 0);
    cudaStreamWaitEvent(s1, eRoot, 0);
    cudaStreamWaitEvent(s2, eRoot, 0);

    // stream 0: pack_nodes -> pack_wb -> proj_val (chain A)
    pack_nodes_kernel<<<128, 256>>>(nodes);
    cudaEventRecord(eN, 0);
    pack_w_kernel<<<384, 256>>>((const float*)d_in[8], 0);   // -> g_wb
    dim3 gpv(64, NH);
    proj_val_mma<<<gpv, 256, PV_SMEM>>>((const float*)d_in[9]);

    // stream 1: pack_wkq -> (wait nodes) -> proj_kq_mma (chain B)
    pack_w_kernel<<<64, 256, 0, s1>>>((const float*)d_in[3], 1);  // -> g_wkq
    cudaStreamWaitEvent(s1, eN, 0);
    dim3 gkq(64, 4);
    proj_kq_mma<<<gkq, 256, KQ_SMEM, s1>>>((const float*)d_in[4]);
    cudaEventRecord(e1, s1);

    // stream 2: pos/rot projections (chain C, independent)
    proj_kq_pr<<<SEQ/16, 256, 0, s2>>>(pos, rot,
        (const float*)d_in[5], (const float*)d_in[6], (const float*)d_in[7]);
    cudaEventRecord(e2, s2);

    // join on stream 0: pack_qb needs g_q complete (chains B + C)
    cudaStreamWaitEvent(0, e1, 0);
    cudaStreamWaitEvent(0, e2, 0);
    pack_qb_kernel<<<1536, 256>>>();

    dim3 ga(SEQ/128, NH);
    attn_kernel<<<ga, 256, SMEM_DYN>>>();
    reduce_kernel<<<(SEQ*ND/2)/256, 256>>>((float*)d_out);

    cudaStreamDestroy(s1);
    cudaStreamDestroy(s2);
    cudaEventDestroy(eRoot);
    cudaEventDestroy(eN);
    cudaEventDestroy(e1);
    cudaEventDestroy(e2);
}